// round 3
// baseline (speedup 1.0000x reference)
#include <cuda_runtime.h>
#include <cuda_bf16.h>
#include <cstddef>

// Problem constants
#define BB 8
#define NN 2048
#define DD 1024
#define CC 1024
#define HH 4096
#define MM (BB*NN)          // 16384
#define EPSF 1e-6f

// ---------------------------------------------------------------------------
// Scratch (device globals; no allocations allowed)
// ---------------------------------------------------------------------------
__device__ float g_nctx[CC * DD];          // normed codebook
__device__ float g_kbuf[CC * DD];          // k (then rope'd in place)
__device__ float g_vbuf[CC * DD];          // v
__device__ float g_bufA[MM * DD];          // normed_q -> attn
__device__ float g_bufB[MM * DD];          // q -> y
__device__ float g_ao[MM * DD];            // attn_out
__device__ float g_h[MM * DD];             // rmsnorm(attn_out)
__device__ float g_t1[(size_t)MM * HH];    // h@w1 -> silu(t1)*t3
__device__ float g_t3[(size_t)MM * HH];    // h@w3

// ---------------------------------------------------------------------------
// Block reductions (256 threads)
// ---------------------------------------------------------------------------
__device__ __forceinline__ float block_reduce_sum(float v) {
    __shared__ float red[8];
    int lane = threadIdx.x & 31, wid = threadIdx.x >> 5;
    #pragma unroll
    for (int o = 16; o > 0; o >>= 1) v += __shfl_down_sync(0xffffffffu, v, o);
    __syncthreads();
    if (lane == 0) red[wid] = v;
    __syncthreads();
    float r = 0.f;
    if (threadIdx.x < 8) r = red[threadIdx.x];
    if (wid == 0) {
        #pragma unroll
        for (int o = 4; o > 0; o >>= 1) r += __shfl_down_sync(0xffu, r, o);
        if (lane == 0) red[0] = r;
    }
    __syncthreads();
    return red[0];
}

__device__ __forceinline__ float block_reduce_max(float v) {
    __shared__ float red[8];
    int lane = threadIdx.x & 31, wid = threadIdx.x >> 5;
    #pragma unroll
    for (int o = 16; o > 0; o >>= 1) v = fmaxf(v, __shfl_down_sync(0xffffffffu, v, o));
    __syncthreads();
    if (lane == 0) red[wid] = v;
    __syncthreads();
    float r = -3.0e38f;
    if (threadIdx.x < 8) r = red[threadIdx.x];
    if (wid == 0) {
        #pragma unroll
        for (int o = 4; o > 0; o >>= 1) r = fmaxf(r, __shfl_down_sync(0xffu, r, o));
        if (lane == 0) red[0] = r;
    }
    __syncthreads();
    return red[0];
}

// ---------------------------------------------------------------------------
// Tiled SGEMM: C[M,N] = alpha * A[M,K] @ B  (+ bias[N]) (+ addm[M,N])
//   TRANSB=false: B is [K,N] row-major
//   TRANSB=true : B is [N,K] row-major (C = A @ B^T)
// All of M, N multiples of 128; K multiple of 8.
// 256 threads, 128x128 tile, 8x8 per-thread micro-tile, BK=8.
// ---------------------------------------------------------------------------
template <bool TRANSB>
__global__ __launch_bounds__(256)
void sgemm_kernel(const float* __restrict__ A, const float* __restrict__ B,
                  float* __restrict__ C, int M, int N, int K, float alpha,
                  const float* __restrict__ bias, const float* __restrict__ addm)
{
    __shared__ float As[8][128];
    __shared__ float Bs[8][128];

    const int bm  = blockIdx.y * 128;
    const int bn  = blockIdx.x * 128;
    const int tid = threadIdx.x;
    const int tx  = tid & 15;    // 0..15 -> col tile
    const int ty  = tid >> 4;    // 0..15 -> row tile

    float acc[8][8];
    #pragma unroll
    for (int i = 0; i < 8; i++)
        #pragma unroll
        for (int j = 0; j < 8; j++) acc[i][j] = 0.f;

    const int lrow = tid >> 1;          // 0..127
    const int lcol = (tid & 1) * 4;     // 0 or 4

    const float* Ap = A + (size_t)(bm + lrow) * K + lcol;
    const float* Bp;
    if (TRANSB) Bp = B + (size_t)(bn + lrow) * K + lcol;
    else        Bp = B + (size_t)(tid >> 5) * N + bn + (tid & 31) * 4;

    for (int k0 = 0; k0 < K; k0 += 8) {
        float4 a4 = *(const float4*)Ap;
        As[lcol + 0][lrow] = a4.x;
        As[lcol + 1][lrow] = a4.y;
        As[lcol + 2][lrow] = a4.z;
        As[lcol + 3][lrow] = a4.w;
        if (TRANSB) {
            float4 b4 = *(const float4*)Bp;
            Bs[lcol + 0][lrow] = b4.x;
            Bs[lcol + 1][lrow] = b4.y;
            Bs[lcol + 2][lrow] = b4.z;
            Bs[lcol + 3][lrow] = b4.w;
            Bp += 8;
        } else {
            float4 b4 = *(const float4*)Bp;
            *(float4*)&Bs[tid >> 5][(tid & 31) * 4] = b4;
            Bp += (size_t)8 * N;
        }
        Ap += 8;
        __syncthreads();

        #pragma unroll
        for (int kk = 0; kk < 8; kk++) {
            float a[8], b[8];
            *(float4*)&a[0] = *(const float4*)&As[kk][ty * 8];
            *(float4*)&a[4] = *(const float4*)&As[kk][ty * 8 + 4];
            *(float4*)&b[0] = *(const float4*)&Bs[kk][tx * 8];
            *(float4*)&b[4] = *(const float4*)&Bs[kk][tx * 8 + 4];
            #pragma unroll
            for (int i = 0; i < 8; i++)
                #pragma unroll
                for (int j = 0; j < 8; j++)
                    acc[i][j] = fmaf(a[i], b[j], acc[i][j]);
        }
        __syncthreads();
    }

    #pragma unroll
    for (int i = 0; i < 8; i++) {
        int row = bm + ty * 8 + i;
        size_t base = (size_t)row * N + bn + tx * 8;
        #pragma unroll
        for (int j = 0; j < 8; j += 4) {
            float4 o;
            o.x = acc[i][j + 0] * alpha;
            o.y = acc[i][j + 1] * alpha;
            o.z = acc[i][j + 2] * alpha;
            o.w = acc[i][j + 3] * alpha;
            if (bias) {
                int col = bn + tx * 8 + j;
                o.x += bias[col + 0]; o.y += bias[col + 1];
                o.z += bias[col + 2]; o.w += bias[col + 3];
            }
            if (addm) {
                float4 ad = *(const float4*)&addm[base + j];
                o.x += ad.x; o.y += ad.y; o.z += ad.z; o.w += ad.w;
            }
            *(float4*)&C[base + j] = o;
        }
    }
}

// ---------------------------------------------------------------------------
// RMSNorm: out[row] = x[row] * rsqrt(mean(x^2)+eps) * g ; rows of length 1024
// One block (256 threads) per row.
// ---------------------------------------------------------------------------
__global__ __launch_bounds__(256)
void rmsnorm_kernel(const float* __restrict__ x, const float* __restrict__ g,
                    float* __restrict__ out)
{
    size_t row = blockIdx.x;
    const float* xr = x + row * DD;
    float* orow = out + row * DD;
    int i = threadIdx.x * 4;
    float4 v = *(const float4*)&xr[i];
    float ss = v.x * v.x + v.y * v.y + v.z * v.z + v.w * v.w;
    ss = block_reduce_sum(ss);
    float inv = rsqrtf(ss * (1.0f / DD) + EPSF);
    float4 gg = *(const float4*)&g[i];
    float4 o;
    o.x = v.x * inv * gg.x; o.y = v.y * inv * gg.y;
    o.z = v.z * inv * gg.z; o.w = v.w * inv * gg.w;
    *(float4*)&orow[i] = o;
}

// ---------------------------------------------------------------------------
// RoPE in place on rows of length 1024 (512 interleaved pairs).
// pos = positions[row].
// inv_freq = 10000^(-j/512) = exp2(-j/512 * log2(10000))
// ---------------------------------------------------------------------------
__global__ __launch_bounds__(256)
void rope_kernel(float* __restrict__ x, const int* __restrict__ positions)
{
    size_t row = blockIdx.x;
    float p = (float)positions[row];
    float* xr = x + row * DD;
    const float LOG2_BASE = 13.28771237954945f;   // log2(10000)
    #pragma unroll
    for (int jj = 0; jj < 2; jj++) {
        int j = threadIdx.x + jj * 256;            // pair index 0..511
        float invf = exp2f(-(float)j * (LOG2_BASE / 512.0f));
        float ang = p * invf;
        float s, c;
        sincosf(ang, &s, &c);
        float x1 = xr[2 * j], x2 = xr[2 * j + 1];
        xr[2 * j]     = x1 * c - x2 * s;
        xr[2 * j + 1] = x1 * s + x2 * c;
    }
}

// ---------------------------------------------------------------------------
// Gumbel + softmax over C=1024. One block per row.
// Reads log_alpha (already /sqrt(D)); writes log_alpha_tau and z.
// ---------------------------------------------------------------------------
__global__ __launch_bounds__(256)
void gumbel_softmax_kernel(const float* __restrict__ la, const float* __restrict__ noise,
                           const float* __restrict__ tau_p, const float* __restrict__ gns_p,
                           float* __restrict__ lat_out, float* __restrict__ z_out)
{
    size_t row = blockIdx.x;
    float tau = *tau_p;
    float gns = *gns_p;
    float inv_tau = 1.0f / tau;
    size_t base = row * CC + threadIdx.x * 4;

    float4 la4 = *(const float4*)&la[base];
    float4 u4  = *(const float4*)&noise[base];
    float lt[4];
    {
        float u[4] = {u4.x, u4.y, u4.z, u4.w};
        float l[4] = {la4.x, la4.y, la4.z, la4.w};
        #pragma unroll
        for (int t = 0; t < 4; t++) {
            float gum = -logf(-logf(u[t] + 1e-10f) + 1e-10f);
            lt[t] = (l[t] + gns * gum) * inv_tau;
        }
    }
    *(float4*)&lat_out[base] = make_float4(lt[0], lt[1], lt[2], lt[3]);

    float m = fmaxf(fmaxf(lt[0], lt[1]), fmaxf(lt[2], lt[3]));
    m = block_reduce_max(m);
    float e[4], s = 0.f;
    #pragma unroll
    for (int t = 0; t < 4; t++) { e[t] = expf(lt[t] - m); s += e[t]; }
    s = block_reduce_sum(s);
    float invs = 1.0f / s;
    *(float4*)&z_out[base] = make_float4(e[0] * invs, e[1] * invs, e[2] * invs, e[3] * invs);
}

// ---------------------------------------------------------------------------
// attn_out = rs*latents + y ; h = rmsnorm(attn_out) * g_ff. One block per row.
// ---------------------------------------------------------------------------
__global__ __launch_bounds__(256)
void residual_rms_kernel(const float* __restrict__ latents, const float* __restrict__ y,
                         const float* __restrict__ rs_p, const float* __restrict__ gff,
                         float* __restrict__ ao_out, float* __restrict__ h_out)
{
    size_t row = blockIdx.x;
    float rs = *rs_p;
    size_t base = row * DD + threadIdx.x * 4;
    float4 l4 = *(const float4*)&latents[base];
    float4 y4 = *(const float4*)&y[base];
    float4 ao;
    ao.x = rs * l4.x + y4.x; ao.y = rs * l4.y + y4.y;
    ao.z = rs * l4.z + y4.z; ao.w = rs * l4.w + y4.w;
    *(float4*)&ao_out[base] = ao;
    float ss = ao.x * ao.x + ao.y * ao.y + ao.z * ao.z + ao.w * ao.w;
    ss = block_reduce_sum(ss);
    float inv = rsqrtf(ss * (1.0f / DD) + EPSF);
    float4 g4 = *(const float4*)&gff[threadIdx.x * 4];
    float4 h;
    h.x = ao.x * inv * g4.x; h.y = ao.y * inv * g4.y;
    h.z = ao.z * inv * g4.z; h.w = ao.w * inv * g4.w;
    *(float4*)&h_out[base] = h;
}

// ---------------------------------------------------------------------------
// t1 = silu(t1) * t3 (elementwise, vectorized, grid-stride)
// ---------------------------------------------------------------------------
__global__ __launch_bounds__(256)
void silu_mul_kernel(float* __restrict__ t1, const float* __restrict__ t3, size_t n)
{
    size_t stride = (size_t)gridDim.x * 256 * 4;
    for (size_t i = ((size_t)blockIdx.x * 256 + threadIdx.x) * 4; i < n; i += stride) {
        float4 a = *(const float4*)&t1[i];
        float4 b = *(const float4*)&t3[i];
        a.x = (a.x / (1.0f + expf(-a.x))) * b.x;
        a.y = (a.y / (1.0f + expf(-a.y))) * b.y;
        a.z = (a.z / (1.0f + expf(-a.z))) * b.z;
        a.w = (a.w / (1.0f + expf(-a.w))) * b.w;
        *(float4*)&t1[i] = a;
    }
}

// ---------------------------------------------------------------------------
// Launch
// ---------------------------------------------------------------------------
extern "C" void kernel_launch(void* const* d_in, const int* in_sizes, int n_in,
                              void* d_out, int out_size)
{
    (void)in_sizes; (void)n_in; (void)out_size;

    const float* latents  = (const float*)d_in[0];
    const float* codebook = (const float*)d_in[1];
    const float* Wq       = (const float*)d_in[2];
    const float* Wk       = (const float*)d_in[3];
    const float* Wv       = (const float*)d_in[4];
    const float* bv       = (const float*)d_in[5];
    const float* Wc       = (const float*)d_in[6];
    const float* w1       = (const float*)d_in[7];
    const float* w2       = (const float*)d_in[8];
    const float* w3       = (const float*)d_in[9];
    const float* gctx     = (const float*)d_in[10];
    const float* gq       = (const float*)d_in[11];
    const float* gff      = (const float*)d_in[12];
    const float* noise    = (const float*)d_in[13];
    const int*   positions= (const int*)d_in[14];
    const float* tau      = (const float*)d_in[15];
    const float* rs       = (const float*)d_in[16];
    const float* gns      = (const float*)d_in[17];

    float *nctx, *kbuf, *vbuf, *bufA, *bufB, *ao, *h, *t1, *t3;
    cudaGetSymbolAddress((void**)&nctx, g_nctx);
    cudaGetSymbolAddress((void**)&kbuf, g_kbuf);
    cudaGetSymbolAddress((void**)&vbuf, g_vbuf);
    cudaGetSymbolAddress((void**)&bufA, g_bufA);
    cudaGetSymbolAddress((void**)&bufB, g_bufB);
    cudaGetSymbolAddress((void**)&ao,   g_ao);
    cudaGetSymbolAddress((void**)&h,    g_h);
    cudaGetSymbolAddress((void**)&t1,   g_t1);
    cudaGetSymbolAddress((void**)&t3,   g_t3);

    float* out_cb  = (float*)d_out;
    float* out_la  = out_cb  + (size_t)MM * DD;
    float* out_lat = out_la  + (size_t)MM * CC;
    float* out_z   = out_lat + (size_t)MM * CC;

    const float inv_scale = 1.0f / 32.0f;   // 1/sqrt(1024)

    // Context path
    rmsnorm_kernel<<<CC, 256>>>(codebook, gctx, nctx);
    sgemm_kernel<false><<<dim3(DD/128, CC/128), 256>>>(nctx, Wk, kbuf, CC, DD, DD, 1.f, nullptr, nullptr);
    sgemm_kernel<false><<<dim3(DD/128, CC/128), 256>>>(nctx, Wv, vbuf, CC, DD, DD, 1.f, bv, nullptr);
    rope_kernel<<<CC, 256>>>(kbuf, positions);

    // Query path
    rmsnorm_kernel<<<MM, 256>>>(latents, gq, bufA);
    sgemm_kernel<false><<<dim3(DD/128, MM/128), 256>>>(bufA, Wq, bufB, MM, DD, DD, 1.f, nullptr, nullptr);
    rope_kernel<<<MM, 256>>>(bufB, positions);

    // log_alpha = q @ k^T / sqrt(D)
    sgemm_kernel<true><<<dim3(CC/128, MM/128), 256>>>(bufB, kbuf, out_la, MM, CC, DD, inv_scale, nullptr, nullptr);

    // gumbel + softmax -> log_alpha_tau, z
    gumbel_softmax_kernel<<<MM, 256>>>(out_la, noise, tau, gns, out_lat, out_z);

    // attn = z @ v ; y = attn @ Wc
    sgemm_kernel<false><<<dim3(DD/128, MM/128), 256>>>(out_z, vbuf, bufA, MM, DD, CC, 1.f, nullptr, nullptr);
    sgemm_kernel<false><<<dim3(DD/128, MM/128), 256>>>(bufA, Wc, bufB, MM, DD, DD, 1.f, nullptr, nullptr);

    // attn_out + rmsnorm
    residual_rms_kernel<<<MM, 256>>>(latents, bufB, rs, gff, ao, h);

    // FFN
    sgemm_kernel<false><<<dim3(HH/128, MM/128), 256>>>(h, w1, t1, MM, HH, DD, 1.f, nullptr, nullptr);
    sgemm_kernel<false><<<dim3(HH/128, MM/128), 256>>>(h, w3, t3, MM, HH, DD, 1.f, nullptr, nullptr);
    silu_mul_kernel<<<4096, 256>>>(t1, t3, (size_t)MM * HH);
    sgemm_kernel<false><<<dim3(DD/128, MM/128), 256>>>(t1, w2, out_cb, MM, DD, HH, 1.f, nullptr, ao);
}

// round 6
// speedup vs baseline: 4.9481x; 4.9481x over previous
#include <cuda_runtime.h>
#include <cuda_bf16.h>
#include <cstdint>
#include <cstddef>

// Problem constants
#define BB 8
#define NN 2048
#define DD 1024
#define CC 1024
#define HH 4096
#define MM (BB*NN)          // 16384
#define EPSF 1e-6f

typedef __nv_bfloat16 bf16;

// ===========================================================================
// Helpers
// ===========================================================================
__device__ __forceinline__ uint32_t smem_u32(const void* p) {
    uint32_t a;
    asm("{ .reg .u64 t; cvta.to.shared.u64 t, %1; cvt.u32.u64 %0, t; }" : "=r"(a) : "l"(p));
    return a;
}
__device__ __forceinline__ void ldsm4(uint32_t* r, uint32_t addr) {
    asm volatile("ldmatrix.sync.aligned.m8n8.x4.shared.b16 {%0,%1,%2,%3}, [%4];"
        : "=r"(r[0]), "=r"(r[1]), "=r"(r[2]), "=r"(r[3]) : "r"(addr));
}
__device__ __forceinline__ void mma16816(float* d, const uint32_t* a, const uint32_t* b) {
    asm volatile("mma.sync.aligned.m16n8k16.row.col.f32.bf16.bf16.f32 "
        "{%0,%1,%2,%3}, {%4,%5,%6,%7}, {%8,%9}, {%0,%1,%2,%3};"
        : "+f"(d[0]), "+f"(d[1]), "+f"(d[2]), "+f"(d[3])
        : "r"(a[0]), "r"(a[1]), "r"(a[2]), "r"(a[3]), "r"(b[0]), "r"(b[1]));
}
__device__ __forceinline__ void cp_async16(uint32_t dst, const void* src) {
    asm volatile("cp.async.cg.shared.global [%0], [%1], 16;"
        :: "r"(dst), "l"(__cvta_generic_to_global(src)));
}
#define CP_COMMIT()  asm volatile("cp.async.commit_group;" ::: "memory")
#define CP_WAIT(n)   asm volatile("cp.async.wait_group %0;" :: "n"(n) : "memory")

__device__ __forceinline__ void split_bf(float x, bf16& h, bf16& l) {
    h = __float2bfloat16(x);
    l = __float2bfloat16(x - __bfloat162float(h));
}
__device__ __forceinline__ uint32_t pack_bf2(bf16 a, bf16 b) {
    __nv_bfloat162 p; p.x = a; p.y = b;
    return *(uint32_t*)&p;
}

// ===========================================================================
// Scratch (device globals)
// ===========================================================================
__device__ __align__(16) bf16 g_wqT_h[DD*DD], g_wqT_l[DD*DD];
__device__ __align__(16) bf16 g_wkT_h[DD*DD], g_wkT_l[DD*DD];
__device__ __align__(16) bf16 g_wvT_h[DD*DD], g_wvT_l[DD*DD];
__device__ __align__(16) bf16 g_wcT_h[DD*DD], g_wcT_l[DD*DD];
__device__ __align__(16) bf16 g_w1T_h[(size_t)HH*DD], g_w1T_l[(size_t)HH*DD];
__device__ __align__(16) bf16 g_w3T_h[(size_t)HH*DD], g_w3T_l[(size_t)HH*DD];
__device__ __align__(16) bf16 g_w2T_h[(size_t)DD*HH], g_w2T_l[(size_t)DD*HH];
__device__ __align__(16) bf16 g_nctx_h[CC*DD], g_nctx_l[CC*DD];
__device__ float g_kf[CC*DD];
__device__ float g_vf[CC*DD];
__device__ __align__(16) bf16 g_k_h[CC*DD], g_k_l[CC*DD];
__device__ __align__(16) bf16 g_vT_h[DD*CC], g_vT_l[DD*CC];
__device__ __align__(16) bf16 g_nq_h[(size_t)MM*DD], g_nq_l[(size_t)MM*DD];
__device__ float g_qf[(size_t)MM*DD];
__device__ __align__(16) bf16 g_q_h[(size_t)MM*DD], g_q_l[(size_t)MM*DD];
__device__ __align__(16) bf16 g_z_h[(size_t)MM*CC], g_z_l[(size_t)MM*CC];
__device__ __align__(16) bf16 g_attn_h[(size_t)MM*DD], g_attn_l[(size_t)MM*DD];
__device__ float g_yf[(size_t)MM*DD];
__device__ float g_ao[(size_t)MM*DD];
__device__ __align__(16) bf16 g_h_h[(size_t)MM*DD], g_h_l[(size_t)MM*DD];
__device__ float g_t1[(size_t)MM*HH];
__device__ float g_t3[(size_t)MM*HH];
__device__ __align__(16) bf16 g_p_h[(size_t)MM*HH], g_p_l[(size_t)MM*HH];

// ===========================================================================
// bf16x3 split GEMM via mma.sync (HMMA): C[M,N] = alpha*A@B^T (+bias)(+addm)
//   A = (Ah,Al) [M,K] row-major bf16; B = (Bh,Bl) [N,K] row-major bf16.
//   If OutH != nullptr: write split bf16 (OutH,OutL) instead of fp32 C.
// 256 threads, CTA tile 128x128, BK=32, double-buffered cp.async.
// SMEM tile pitch = 40 bf16 (80 B) -> conflict-free ldmatrix.
// ===========================================================================
#define TILE_ELEMS (128 * 40)                 // 5120 bf16 = 10240 B
#define STAGE_ELEMS (4 * TILE_ELEMS)          // Ah,Al,Bh,Bl
#define GEMM_SMEM_BYTES (2 * STAGE_ELEMS * 2) // 81920 B

__device__ __forceinline__ void stage_load(
    uint32_t sm_stage, const bf16* __restrict__ Ah, const bf16* __restrict__ Al,
    const bf16* __restrict__ Bh, const bf16* __restrict__ Bl,
    int bm, int bn, int K, int k0, int tid)
{
    #pragma unroll
    for (int t = 0; t < 4; t++) {
        const bf16* gb = (t == 0) ? Ah : (t == 1) ? Al : (t == 2) ? Bh : Bl;
        const int brow = (t < 2) ? bm : bn;
        gb += (size_t)brow * K + k0;
        const uint32_t sb = sm_stage + t * (TILE_ELEMS * 2);
        #pragma unroll
        for (int j = 0; j < 2; j++) {
            const int c = tid + j * 256;
            const int row = c >> 2, ch = c & 3;
            cp_async16(sb + row * 80 + ch * 16, gb + (size_t)row * K + ch * 8);
        }
    }
}

__global__ __launch_bounds__(256, 1)
void bf3_gemm(const bf16* __restrict__ Ah, const bf16* __restrict__ Al,
              const bf16* __restrict__ Bh, const bf16* __restrict__ Bl,
              float* __restrict__ Cf, bf16* __restrict__ OutH, bf16* __restrict__ OutL,
              int M, int N, int K, float alpha,
              const float* __restrict__ bias, const float* __restrict__ addm)
{
    extern __shared__ char smem[];
    const uint32_t sb = smem_u32(smem);
    const int tid = threadIdx.x, wid = tid >> 5, lane = tid & 31;
    const int bm = blockIdx.y * 128, bn = blockIdx.x * 128;
    const int wm = (wid >> 1) * 32, wn = (wid & 1) * 64;

    float acc[2][8][4];
    #pragma unroll
    for (int i = 0; i < 2; i++)
        #pragma unroll
        for (int j = 0; j < 8; j++)
            #pragma unroll
            for (int q = 0; q < 4; q++) acc[i][j][q] = 0.f;

    // ldmatrix lane address offsets (bytes within a tile)
    const uint32_t aoff = (uint32_t)((wm + (lane & 15)) * 80 + (lane >> 4) * 16);
    const uint32_t boff = (uint32_t)((wn + (lane & 7) + ((lane >> 4) & 1) * 8) * 80
                                     + ((lane >> 3) & 1) * 16);

    const int S = K >> 5;   // K/32 stages
    stage_load(sb, Ah, Al, Bh, Bl, bm, bn, K, 0, tid);
    CP_COMMIT();

    for (int s = 0; s < S; s++) {
        if (s + 1 < S) {
            stage_load(sb + ((s + 1) & 1) * (STAGE_ELEMS * 2),
                       Ah, Al, Bh, Bl, bm, bn, K, (s + 1) << 5, tid);
            CP_COMMIT();
            CP_WAIT(1);
        } else {
            CP_WAIT(0);
        }
        __syncthreads();

        const uint32_t stg = sb + (s & 1) * (STAGE_ELEMS * 2);
        const uint32_t tAh = stg;
        const uint32_t tAl = stg + TILE_ELEMS * 2;
        const uint32_t tBh = stg + 2 * TILE_ELEMS * 2;
        const uint32_t tBl = stg + 3 * TILE_ELEMS * 2;

        #pragma unroll
        for (int ks = 0; ks < 2; ks++) {
            const uint32_t ko = ks * 32;   // byte offset for k16 step
            uint32_t a[2][2][4];           // [split][mt]
            uint32_t b[2][4][4];           // [split][bt] (each = two n8 tiles)
            #pragma unroll
            for (int mt = 0; mt < 2; mt++) {
                ldsm4(a[0][mt], tAh + aoff + mt * (16 * 80) + ko);
                ldsm4(a[1][mt], tAl + aoff + mt * (16 * 80) + ko);
            }
            #pragma unroll
            for (int bt = 0; bt < 4; bt++) {
                ldsm4(b[0][bt], tBh + boff + bt * (16 * 80) + ko);
                ldsm4(b[1][bt], tBl + boff + bt * (16 * 80) + ko);
            }
            #pragma unroll
            for (int mt = 0; mt < 2; mt++)
                #pragma unroll
                for (int bt = 0; bt < 4; bt++)
                    #pragma unroll
                    for (int hf = 0; hf < 2; hf++) {
                        const int nt = bt * 2 + hf;
                        mma16816(acc[mt][nt], a[0][mt], &b[0][bt][hf * 2]);  // Ah*Bh
                        mma16816(acc[mt][nt], a[0][mt], &b[1][bt][hf * 2]);  // Ah*Bl
                        mma16816(acc[mt][nt], a[1][mt], &b[0][bt][hf * 2]);  // Al*Bh
                    }
        }
        __syncthreads();
    }

    // ---- epilogue ----
    const int g = lane >> 2, qd = lane & 3;
    #pragma unroll
    for (int mt = 0; mt < 2; mt++) {
        const int r0 = bm + wm + mt * 16 + g;
        #pragma unroll
        for (int nt = 0; nt < 8; nt++) {
            const int col = bn + wn + nt * 8 + qd * 2;
            #pragma unroll
            for (int half = 0; half < 2; half++) {
                const int row = r0 + half * 8;
                float x0 = acc[mt][nt][half * 2 + 0] * alpha;
                float x1 = acc[mt][nt][half * 2 + 1] * alpha;
                const size_t idx = (size_t)row * N + col;
                if (OutH) {
                    bf16 h0, l0, h1, l1;
                    split_bf(x0, h0, l0);
                    split_bf(x1, h1, l1);
                    *(uint32_t*)(OutH + idx) = pack_bf2(h0, h1);
                    *(uint32_t*)(OutL + idx) = pack_bf2(l0, l1);
                } else {
                    if (bias) { x0 += bias[col]; x1 += bias[col + 1]; }
                    if (addm) {
                        const float2 a2 = *(const float2*)&addm[idx];
                        x0 += a2.x; x1 += a2.y;
                    }
                    *(float2*)&Cf[idx] = make_float2(x0, x1);
                }
            }
        }
    }
}

// ===========================================================================
// Transpose + split: src fp32 [R,C] -> (dh,dl) bf16 [C,R]
// ===========================================================================
__global__ __launch_bounds__(256)
void transconv_kernel(const float* __restrict__ src, int R, int C,
                      bf16* __restrict__ dh, bf16* __restrict__ dl)
{
    __shared__ float t[32][33];
    const int c0 = blockIdx.x * 32, r0 = blockIdx.y * 32;
    const int tx = threadIdx.x & 31, ty = threadIdx.x >> 5;  // block 32x8
    #pragma unroll
    for (int i = 0; i < 4; i++)
        t[ty + i * 8][tx] = src[(size_t)(r0 + ty + i * 8) * C + c0 + tx];
    __syncthreads();
    #pragma unroll
    for (int i = 0; i < 4; i++) {
        const float x = t[tx][ty + i * 8];
        bf16 h, l; split_bf(x, h, l);
        const size_t idx = (size_t)(c0 + ty + i * 8) * R + r0 + tx;
        dh[idx] = h; dl[idx] = l;
    }
}

// ===========================================================================
// Block reductions (256 threads)
// ===========================================================================
__device__ __forceinline__ float block_reduce_sum(float v) {
    __shared__ float red[8];
    const int lane = threadIdx.x & 31, wid = threadIdx.x >> 5;
    #pragma unroll
    for (int o = 16; o > 0; o >>= 1) v += __shfl_down_sync(0xffffffffu, v, o);
    __syncthreads();
    if (lane == 0) red[wid] = v;
    __syncthreads();
    float r = 0.f;
    if (threadIdx.x < 8) r = red[threadIdx.x];
    if (wid == 0) {
        #pragma unroll
        for (int o = 4; o > 0; o >>= 1) r += __shfl_down_sync(0xffu, r, o);
        if (lane == 0) red[0] = r;
    }
    __syncthreads();
    return red[0];
}
__device__ __forceinline__ float block_reduce_max(float v) {
    __shared__ float red[8];
    const int lane = threadIdx.x & 31, wid = threadIdx.x >> 5;
    #pragma unroll
    for (int o = 16; o > 0; o >>= 1) v = fmaxf(v, __shfl_down_sync(0xffffffffu, v, o));
    __syncthreads();
    if (lane == 0) red[wid] = v;
    __syncthreads();
    float r = -3.0e38f;
    if (threadIdx.x < 8) r = red[threadIdx.x];
    if (wid == 0) {
        #pragma unroll
        for (int o = 4; o > 0; o >>= 1) r = fmaxf(r, __shfl_down_sync(0xffu, r, o));
        if (lane == 0) red[0] = r;
    }
    __syncthreads();
    return red[0];
}

// ===========================================================================
// RMSNorm -> split bf16 output. One block (256 thr) per row of 1024.
// ===========================================================================
__global__ __launch_bounds__(256)
void rmsnorm_bf_kernel(const float* __restrict__ x, const float* __restrict__ g,
                       bf16* __restrict__ oh, bf16* __restrict__ ol)
{
    const size_t row = blockIdx.x;
    const int i = threadIdx.x * 4;
    const float4 v = *(const float4*)&x[row * DD + i];
    float ss = v.x*v.x + v.y*v.y + v.z*v.z + v.w*v.w;
    ss = block_reduce_sum(ss);
    const float inv = rsqrtf(ss * (1.0f / DD) + EPSF);
    const float4 gg = *(const float4*)&g[i];
    const float o0 = v.x*inv*gg.x, o1 = v.y*inv*gg.y, o2 = v.z*inv*gg.z, o3 = v.w*inv*gg.w;
    bf16 h0,l0,h1,l1,h2,l2,h3,l3;
    split_bf(o0,h0,l0); split_bf(o1,h1,l1); split_bf(o2,h2,l2); split_bf(o3,h3,l3);
    const size_t idx = row * DD + i;
    *(uint2*)(oh + idx) = make_uint2(pack_bf2(h0,h1), pack_bf2(h2,h3));
    *(uint2*)(ol + idx) = make_uint2(pack_bf2(l0,l1), pack_bf2(l2,l3));
}

// ===========================================================================
// RoPE: read fp32, write split bf16. 512 pairs per row of 1024.
// ===========================================================================
__global__ __launch_bounds__(256)
void rope_bf_kernel(const float* __restrict__ x, const int* __restrict__ positions,
                    bf16* __restrict__ oh, bf16* __restrict__ ol)
{
    const size_t row = blockIdx.x;
    const float p = (float)positions[row];
    const float* xr = x + row * DD;
    const float L2B = 13.28771237954945f;  // log2(10000)
    #pragma unroll
    for (int jj = 0; jj < 2; jj++) {
        const int j = threadIdx.x + jj * 256;   // pair index
        const float invf = exp2f(-(float)j * (L2B / 512.0f));
        float s, c;
        sincosf(p * invf, &s, &c);
        const float x1 = xr[2*j], x2 = xr[2*j + 1];
        const float r1 = x1 * c - x2 * s;
        const float r2 = x1 * s + x2 * c;
        bf16 h1, l1, h2, l2;
        split_bf(r1, h1, l1); split_bf(r2, h2, l2);
        const size_t idx = row * DD + 2*j;
        *(uint32_t*)(oh + idx) = pack_bf2(h1, h2);
        *(uint32_t*)(ol + idx) = pack_bf2(l1, l2);
    }
}

// ===========================================================================
// Gumbel + softmax over C=1024; writes log_alpha_tau, z (fp32) and z split bf16.
// ===========================================================================
__global__ __launch_bounds__(256)
void gumbel_softmax_kernel(const float* __restrict__ la, const float* __restrict__ noise,
                           const float* __restrict__ tau_p, const float* __restrict__ gns_p,
                           float* __restrict__ lat_out, float* __restrict__ z_out,
                           bf16* __restrict__ zh, bf16* __restrict__ zl)
{
    const size_t row = blockIdx.x;
    const float inv_tau = 1.0f / (*tau_p);
    const float gns = *gns_p;
    const size_t base = row * CC + threadIdx.x * 4;

    const float4 la4 = *(const float4*)&la[base];
    const float4 u4  = *(const float4*)&noise[base];
    float lt[4];
    const float u[4] = {u4.x, u4.y, u4.z, u4.w};
    const float l[4] = {la4.x, la4.y, la4.z, la4.w};
    #pragma unroll
    for (int t = 0; t < 4; t++) {
        const float gum = -logf(-logf(u[t] + 1e-10f) + 1e-10f);
        lt[t] = (l[t] + gns * gum) * inv_tau;
    }
    *(float4*)&lat_out[base] = make_float4(lt[0], lt[1], lt[2], lt[3]);

    float m = fmaxf(fmaxf(lt[0], lt[1]), fmaxf(lt[2], lt[3]));
    m = block_reduce_max(m);
    float e[4], s = 0.f;
    #pragma unroll
    for (int t = 0; t < 4; t++) { e[t] = expf(lt[t] - m); s += e[t]; }
    s = block_reduce_sum(s);
    const float invs = 1.0f / s;
    float z[4];
    #pragma unroll
    for (int t = 0; t < 4; t++) z[t] = e[t] * invs;
    *(float4*)&z_out[base] = make_float4(z[0], z[1], z[2], z[3]);
    bf16 h0,l0,h1,l1,h2,l2,h3,l3;
    split_bf(z[0],h0,l0); split_bf(z[1],h1,l1); split_bf(z[2],h2,l2); split_bf(z[3],h3,l3);
    *(uint2*)(zh + base) = make_uint2(pack_bf2(h0,h1), pack_bf2(h2,h3));
    *(uint2*)(zl + base) = make_uint2(pack_bf2(l0,l1), pack_bf2(l2,l3));
}

// ===========================================================================
// attn_out = rs*latents + y ; h = rmsnorm(attn_out)*g_ff -> split bf16.
// ===========================================================================
__global__ __launch_bounds__(256)
void residual_rms_kernel(const float* __restrict__ latents, const float* __restrict__ y,
                         const float* __restrict__ rs_p, const float* __restrict__ gff,
                         float* __restrict__ ao_out, bf16* __restrict__ hh, bf16* __restrict__ hl)
{
    const size_t row = blockIdx.x;
    const float rs = *rs_p;
    const size_t base = row * DD + threadIdx.x * 4;
    const float4 l4 = *(const float4*)&latents[base];
    const float4 y4 = *(const float4*)&y[base];
    float4 ao;
    ao.x = rs*l4.x + y4.x; ao.y = rs*l4.y + y4.y;
    ao.z = rs*l4.z + y4.z; ao.w = rs*l4.w + y4.w;
    *(float4*)&ao_out[base] = ao;
    float ss = ao.x*ao.x + ao.y*ao.y + ao.z*ao.z + ao.w*ao.w;
    ss = block_reduce_sum(ss);
    const float inv = rsqrtf(ss * (1.0f / DD) + EPSF);
    const float4 g4 = *(const float4*)&gff[threadIdx.x * 4];
    const float h0 = ao.x*inv*g4.x, h1 = ao.y*inv*g4.y, h2 = ao.z*inv*g4.z, h3 = ao.w*inv*g4.w;
    bf16 a0,b0,a1,b1,a2,b2,a3,b3;
    split_bf(h0,a0,b0); split_bf(h1,a1,b1); split_bf(h2,a2,b2); split_bf(h3,a3,b3);
    *(uint2*)(hh + base) = make_uint2(pack_bf2(a0,a1), pack_bf2(a2,a3));
    *(uint2*)(hl + base) = make_uint2(pack_bf2(b0,b1), pack_bf2(b2,b3));
}

// ===========================================================================
// prod = silu(t1) * t3 -> split bf16
// ===========================================================================
__global__ __launch_bounds__(256)
void silu_mul_bf_kernel(const float* __restrict__ t1, const float* __restrict__ t3,
                        bf16* __restrict__ ph, bf16* __restrict__ pl, size_t n)
{
    const size_t stride = (size_t)gridDim.x * 256 * 4;
    for (size_t i = ((size_t)blockIdx.x * 256 + threadIdx.x) * 4; i < n; i += stride) {
        const float4 a = *(const float4*)&t1[i];
        const float4 b = *(const float4*)&t3[i];
        float p[4];
        p[0] = (a.x / (1.0f + expf(-a.x))) * b.x;
        p[1] = (a.y / (1.0f + expf(-a.y))) * b.y;
        p[2] = (a.z / (1.0f + expf(-a.z))) * b.z;
        p[3] = (a.w / (1.0f + expf(-a.w))) * b.w;
        bf16 h0,l0,h1,l1,h2,l2,h3,l3;
        split_bf(p[0],h0,l0); split_bf(p[1],h1,l1); split_bf(p[2],h2,l2); split_bf(p[3],h3,l3);
        *(uint2*)(ph + i) = make_uint2(pack_bf2(h0,h1), pack_bf2(h2,h3));
        *(uint2*)(pl + i) = make_uint2(pack_bf2(l0,l1), pack_bf2(l2,l3));
    }
}

// ===========================================================================
// Launch
// ===========================================================================
extern "C" void kernel_launch(void* const* d_in, const int* in_sizes, int n_in,
                              void* d_out, int out_size)
{
    (void)in_sizes; (void)n_in; (void)out_size;

    const float* latents  = (const float*)d_in[0];
    const float* codebook = (const float*)d_in[1];
    const float* Wq       = (const float*)d_in[2];
    const float* Wk       = (const float*)d_in[3];
    const float* Wv       = (const float*)d_in[4];
    const float* bv       = (const float*)d_in[5];
    const float* Wc       = (const float*)d_in[6];
    const float* w1       = (const float*)d_in[7];
    const float* w2       = (const float*)d_in[8];
    const float* w3       = (const float*)d_in[9];
    const float* gctx     = (const float*)d_in[10];
    const float* gq       = (const float*)d_in[11];
    const float* gff      = (const float*)d_in[12];
    const float* noise    = (const float*)d_in[13];
    const int*   positions= (const int*)d_in[14];
    const float* tau      = (const float*)d_in[15];
    const float* rs       = (const float*)d_in[16];
    const float* gns      = (const float*)d_in[17];

    cudaFuncSetAttribute(bf3_gemm, cudaFuncAttributeMaxDynamicSharedMemorySize, GEMM_SMEM_BYTES);

    #define SYM(v, s) do { void* _p; cudaGetSymbolAddress(&_p, s); v = (decltype(v))_p; } while (0)
    bf16 *wqT_h,*wqT_l,*wkT_h,*wkT_l,*wvT_h,*wvT_l,*wcT_h,*wcT_l;
    bf16 *w1T_h,*w1T_l,*w3T_h,*w3T_l,*w2T_h,*w2T_l;
    bf16 *nctx_h,*nctx_l,*k_h,*k_l,*vT_h,*vT_l,*nq_h,*nq_l,*q_h,*q_l;
    bf16 *z_h,*z_l,*attn_h,*attn_l,*h_h,*h_l,*p_h,*p_l;
    float *kf,*vf,*qf,*yf,*ao,*t1,*t3;
    SYM(wqT_h,g_wqT_h); SYM(wqT_l,g_wqT_l); SYM(wkT_h,g_wkT_h); SYM(wkT_l,g_wkT_l);
    SYM(wvT_h,g_wvT_h); SYM(wvT_l,g_wvT_l); SYM(wcT_h,g_wcT_h); SYM(wcT_l,g_wcT_l);
    SYM(w1T_h,g_w1T_h); SYM(w1T_l,g_w1T_l); SYM(w3T_h,g_w3T_h); SYM(w3T_l,g_w3T_l);
    SYM(w2T_h,g_w2T_h); SYM(w2T_l,g_w2T_l);
    SYM(nctx_h,g_nctx_h); SYM(nctx_l,g_nctx_l);
    SYM(k_h,g_k_h); SYM(k_l,g_k_l); SYM(vT_h,g_vT_h); SYM(vT_l,g_vT_l);
    SYM(nq_h,g_nq_h); SYM(nq_l,g_nq_l); SYM(q_h,g_q_h); SYM(q_l,g_q_l);
    SYM(z_h,g_z_h); SYM(z_l,g_z_l); SYM(attn_h,g_attn_h); SYM(attn_l,g_attn_l);
    SYM(h_h,g_h_h); SYM(h_l,g_h_l); SYM(p_h,g_p_h); SYM(p_l,g_p_l);
    SYM(kf,g_kf); SYM(vf,g_vf); SYM(qf,g_qf); SYM(yf,g_yf); SYM(ao,g_ao);
    SYM(t1,g_t1); SYM(t3,g_t3);
    #undef SYM

    float* out_cb  = (float*)d_out;
    float* out_la  = out_cb  + (size_t)MM * DD;
    float* out_lat = out_la  + (size_t)MM * CC;
    float* out_z   = out_lat + (size_t)MM * CC;

    const float inv_scale = 1.0f / 32.0f;   // 1/sqrt(1024)

    // --- weight transpose + split ---
    transconv_kernel<<<dim3(DD/32, DD/32), 256>>>(Wq, DD, DD, wqT_h, wqT_l);
    transconv_kernel<<<dim3(DD/32, DD/32), 256>>>(Wk, DD, DD, wkT_h, wkT_l);
    transconv_kernel<<<dim3(DD/32, DD/32), 256>>>(Wv, DD, DD, wvT_h, wvT_l);
    transconv_kernel<<<dim3(DD/32, DD/32), 256>>>(Wc, DD, DD, wcT_h, wcT_l);
    transconv_kernel<<<dim3(HH/32, DD/32), 256>>>(w1, DD, HH, w1T_h, w1T_l);
    transconv_kernel<<<dim3(HH/32, DD/32), 256>>>(w3, DD, HH, w3T_h, w3T_l);
    transconv_kernel<<<dim3(DD/32, HH/32), 256>>>(w2, HH, DD, w2T_h, w2T_l);

    // --- context path ---
    rmsnorm_bf_kernel<<<CC, 256>>>(codebook, gctx, nctx_h, nctx_l);
    bf3_gemm<<<dim3(DD/128, CC/128), 256, GEMM_SMEM_BYTES>>>(
        nctx_h, nctx_l, wkT_h, wkT_l, kf, nullptr, nullptr, CC, DD, DD, 1.f, nullptr, nullptr);
    bf3_gemm<<<dim3(DD/128, CC/128), 256, GEMM_SMEM_BYTES>>>(
        nctx_h, nctx_l, wvT_h, wvT_l, vf, nullptr, nullptr, CC, DD, DD, 1.f, bv, nullptr);
    rope_bf_kernel<<<CC, 256>>>(kf, positions, k_h, k_l);
    transconv_kernel<<<dim3(DD/32, CC/32), 256>>>(vf, CC, DD, vT_h, vT_l);

    // --- query path ---
    rmsnorm_bf_kernel<<<MM, 256>>>(latents, gq, nq_h, nq_l);
    bf3_gemm<<<dim3(DD/128, MM/128), 256, GEMM_SMEM_BYTES>>>(
        nq_h, nq_l, wqT_h, wqT_l, qf, nullptr, nullptr, MM, DD, DD, 1.f, nullptr, nullptr);
    rope_bf_kernel<<<MM, 256>>>(qf, positions, q_h, q_l);

    // log_alpha = q @ k^T / 32
    bf3_gemm<<<dim3(CC/128, MM/128), 256, GEMM_SMEM_BYTES>>>(
        q_h, q_l, k_h, k_l, out_la, nullptr, nullptr, MM, CC, DD, inv_scale, nullptr, nullptr);

    // gumbel + softmax
    gumbel_softmax_kernel<<<MM, 256>>>(out_la, noise, tau, gns, out_lat, out_z, z_h, z_l);

    // attn = z @ v (split bf16 out) ; y = attn @ Wc
    bf3_gemm<<<dim3(DD/128, MM/128), 256, GEMM_SMEM_BYTES>>>(
        z_h, z_l, vT_h, vT_l, nullptr, attn_h, attn_l, MM, DD, CC, 1.f, nullptr, nullptr);
    bf3_gemm<<<dim3(DD/128, MM/128), 256, GEMM_SMEM_BYTES>>>(
        attn_h, attn_l, wcT_h, wcT_l, yf, nullptr, nullptr, MM, DD, DD, 1.f, nullptr, nullptr);

    // residual + rmsnorm
    residual_rms_kernel<<<MM, 256>>>(latents, yf, rs, gff, ao, h_h, h_l);

    // FFN
    bf3_gemm<<<dim3(HH/128, MM/128), 256, GEMM_SMEM_BYTES>>>(
        h_h, h_l, w1T_h, w1T_l, t1, nullptr, nullptr, MM, HH, DD, 1.f, nullptr, nullptr);
    bf3_gemm<<<dim3(HH/128, MM/128), 256, GEMM_SMEM_BYTES>>>(
        h_h, h_l, w3T_h, w3T_l, t3, nullptr, nullptr, MM, HH, DD, 1.f, nullptr, nullptr);
    silu_mul_bf_kernel<<<4096, 256>>>(t1, t3, p_h, p_l, (size_t)MM * HH);
    bf3_gemm<<<dim3(DD/128, MM/128), 256, GEMM_SMEM_BYTES>>>(
        p_h, p_l, w2T_h, w2T_l, out_cb, nullptr, nullptr, MM, DD, HH, 1.f, nullptr, ao);
}

// round 7
// speedup vs baseline: 5.0716x; 1.0250x over previous
#include <cuda_runtime.h>
#include <cuda_bf16.h>
#include <cstdint>
#include <cstddef>

// Problem constants
#define BB 8
#define NN 2048
#define DD 1024
#define CC 1024
#define HH 4096
#define HH2 (2*HH)          // fused w1|w3 output width
#define MM (BB*NN)          // 16384
#define EPSF 1e-6f

typedef __nv_bfloat16 bf16;

// ===========================================================================
// Helpers
// ===========================================================================
__device__ __forceinline__ uint32_t smem_u32(const void* p) {
    uint32_t a;
    asm("{ .reg .u64 t; cvta.to.shared.u64 t, %1; cvt.u32.u64 %0, t; }" : "=r"(a) : "l"(p));
    return a;
}
__device__ __forceinline__ void ldsm4(uint32_t* r, uint32_t addr) {
    asm volatile("ldmatrix.sync.aligned.m8n8.x4.shared.b16 {%0,%1,%2,%3}, [%4];"
        : "=r"(r[0]), "=r"(r[1]), "=r"(r[2]), "=r"(r[3]) : "r"(addr));
}
__device__ __forceinline__ void mma16816(float* d, const uint32_t* a, const uint32_t* b) {
    asm volatile("mma.sync.aligned.m16n8k16.row.col.f32.bf16.bf16.f32 "
        "{%0,%1,%2,%3}, {%4,%5,%6,%7}, {%8,%9}, {%0,%1,%2,%3};"
        : "+f"(d[0]), "+f"(d[1]), "+f"(d[2]), "+f"(d[3])
        : "r"(a[0]), "r"(a[1]), "r"(a[2]), "r"(a[3]), "r"(b[0]), "r"(b[1]));
}
__device__ __forceinline__ void cp_async16(uint32_t dst, const void* src) {
    asm volatile("cp.async.cg.shared.global [%0], [%1], 16;"
        :: "r"(dst), "l"(__cvta_generic_to_global(src)));
}
#define CP_COMMIT()  asm volatile("cp.async.commit_group;" ::: "memory")
#define CP_WAIT(n)   asm volatile("cp.async.wait_group %0;" :: "n"(n) : "memory")

__device__ __forceinline__ void split_bf(float x, bf16& h, bf16& l) {
    h = __float2bfloat16(x);
    l = __float2bfloat16(x - __bfloat162float(h));
}
__device__ __forceinline__ uint32_t pack_bf2(bf16 a, bf16 b) {
    __nv_bfloat162 p; p.x = a; p.y = b;
    return *(uint32_t*)&p;
}

// ===========================================================================
// Scratch (device globals)
// ===========================================================================
__device__ __align__(16) bf16 g_wqT_h[DD*DD], g_wqT_l[DD*DD];
__device__ __align__(16) bf16 g_wkT_h[DD*DD], g_wkT_l[DD*DD];
__device__ __align__(16) bf16 g_wvT_h[DD*DD], g_wvT_l[DD*DD];
__device__ __align__(16) bf16 g_wcT_h[DD*DD], g_wcT_l[DD*DD];
__device__ __align__(16) bf16 g_w13T_h[(size_t)HH2*DD], g_w13T_l[(size_t)HH2*DD];
__device__ __align__(16) bf16 g_w2T_h[(size_t)DD*HH], g_w2T_l[(size_t)DD*HH];
__device__ __align__(16) bf16 g_nctx_h[CC*DD], g_nctx_l[CC*DD];
__device__ float g_kf[CC*DD];
__device__ float g_vf[CC*DD];
__device__ __align__(16) bf16 g_k_h[CC*DD], g_k_l[CC*DD];
__device__ __align__(16) bf16 g_vT_h[DD*CC], g_vT_l[DD*CC];
__device__ __align__(16) bf16 g_nq_h[(size_t)MM*DD], g_nq_l[(size_t)MM*DD];
__device__ float g_qf[(size_t)MM*DD];
__device__ __align__(16) bf16 g_q_h[(size_t)MM*DD], g_q_l[(size_t)MM*DD];
__device__ __align__(16) bf16 g_z_h[(size_t)MM*CC], g_z_l[(size_t)MM*CC];
__device__ __align__(16) bf16 g_attn_h[(size_t)MM*DD], g_attn_l[(size_t)MM*DD];
__device__ float g_yf[(size_t)MM*DD];
__device__ float g_ao[(size_t)MM*DD];
__device__ __align__(16) bf16 g_h_h[(size_t)MM*DD], g_h_l[(size_t)MM*DD];
__device__ float g_t13[(size_t)MM*HH2];
__device__ __align__(16) bf16 g_p_h[(size_t)MM*HH], g_p_l[(size_t)MM*HH];
__device__ float g_invf[512];

// ===========================================================================
// bf16x3 split GEMM via mma.sync (HMMA): C[M,N] = alpha*A@B^T (+bias)(+addm)
//   A = (Ah,Al) [M,K] row-major bf16; B = (Bh,Bl) [N,K] row-major bf16.
//   If OutH != nullptr: write split bf16 (OutH,OutL) instead of fp32 C.
// 256 threads, CTA tile 128x128, BK=32, 3-stage cp.async pipeline.
// SMEM tile pitch = 40 bf16 (80 B) -> conflict-free ldmatrix.
// ===========================================================================
#define TILE_ELEMS (128 * 40)                 // 5120 bf16 = 10240 B
#define STAGE_ELEMS (4 * TILE_ELEMS)          // Ah,Al,Bh,Bl
#define STAGE_BYTES (STAGE_ELEMS * 2)         // 40960 B
#define NSTAGE 3
#define GEMM_SMEM_BYTES (NSTAGE * STAGE_BYTES) // 122880 B

__device__ __forceinline__ void stage_load(
    uint32_t sm_stage, const bf16* __restrict__ Ah, const bf16* __restrict__ Al,
    const bf16* __restrict__ Bh, const bf16* __restrict__ Bl,
    int bm, int bn, int K, int k0, int tid)
{
    #pragma unroll
    for (int t = 0; t < 4; t++) {
        const bf16* gb = (t == 0) ? Ah : (t == 1) ? Al : (t == 2) ? Bh : Bl;
        const int brow = (t < 2) ? bm : bn;
        gb += (size_t)brow * K + k0;
        const uint32_t sb = sm_stage + t * (TILE_ELEMS * 2);
        #pragma unroll
        for (int j = 0; j < 2; j++) {
            const int c = tid + j * 256;
            const int row = c >> 2, ch = c & 3;
            cp_async16(sb + row * 80 + ch * 16, gb + (size_t)row * K + ch * 8);
        }
    }
}

__global__ __launch_bounds__(256, 1)
void bf3_gemm(const bf16* __restrict__ Ah, const bf16* __restrict__ Al,
              const bf16* __restrict__ Bh, const bf16* __restrict__ Bl,
              float* __restrict__ Cf, bf16* __restrict__ OutH, bf16* __restrict__ OutL,
              int M, int N, int K, float alpha,
              const float* __restrict__ bias, const float* __restrict__ addm)
{
    extern __shared__ char smem[];
    const uint32_t sb = smem_u32(smem);
    const int tid = threadIdx.x, wid = tid >> 5, lane = tid & 31;
    const int bm = blockIdx.y * 128, bn = blockIdx.x * 128;
    const int wm = (wid >> 1) * 32, wn = (wid & 1) * 64;

    float acc[2][8][4];
    #pragma unroll
    for (int i = 0; i < 2; i++)
        #pragma unroll
        for (int j = 0; j < 8; j++)
            #pragma unroll
            for (int q = 0; q < 4; q++) acc[i][j][q] = 0.f;

    const uint32_t aoff = (uint32_t)((wm + (lane & 15)) * 80 + (lane >> 4) * 16);
    const uint32_t boff = (uint32_t)((wn + (lane & 7) + ((lane >> 4) & 1) * 8) * 80
                                     + ((lane >> 3) & 1) * 16);

    const int S = K >> 5;   // K/32 stages (>= 32 for all our GEMMs)
    stage_load(sb, Ah, Al, Bh, Bl, bm, bn, K, 0, tid);
    CP_COMMIT();
    stage_load(sb + STAGE_BYTES, Ah, Al, Bh, Bl, bm, bn, K, 32, tid);
    CP_COMMIT();

    int buf = 0;            // buffer index of stage s
    int nxt = 2 % NSTAGE;   // buffer index of stage s+2
    for (int s = 0; s < S; s++) {
        if (s + 2 < S)
            stage_load(sb + nxt * STAGE_BYTES, Ah, Al, Bh, Bl, bm, bn, K, (s + 2) << 5, tid);
        CP_COMMIT();        // uniform group count (may be empty)
        CP_WAIT(2);         // stage s resident
        __syncthreads();

        const uint32_t stg = sb + buf * STAGE_BYTES;
        const uint32_t tAh = stg;
        const uint32_t tAl = stg + TILE_ELEMS * 2;
        const uint32_t tBh = stg + 2 * TILE_ELEMS * 2;
        const uint32_t tBl = stg + 3 * TILE_ELEMS * 2;

        #pragma unroll
        for (int ks = 0; ks < 2; ks++) {
            const uint32_t ko = ks * 32;
            uint32_t a[2][2][4];
            uint32_t b[2][4][4];
            #pragma unroll
            for (int mt = 0; mt < 2; mt++) {
                ldsm4(a[0][mt], tAh + aoff + mt * (16 * 80) + ko);
                ldsm4(a[1][mt], tAl + aoff + mt * (16 * 80) + ko);
            }
            #pragma unroll
            for (int bt = 0; bt < 4; bt++) {
                ldsm4(b[0][bt], tBh + boff + bt * (16 * 80) + ko);
                ldsm4(b[1][bt], tBl + boff + bt * (16 * 80) + ko);
            }
            #pragma unroll
            for (int mt = 0; mt < 2; mt++)
                #pragma unroll
                for (int bt = 0; bt < 4; bt++)
                    #pragma unroll
                    for (int hf = 0; hf < 2; hf++) {
                        const int nt = bt * 2 + hf;
                        mma16816(acc[mt][nt], a[0][mt], &b[0][bt][hf * 2]);  // Ah*Bh
                        mma16816(acc[mt][nt], a[0][mt], &b[1][bt][hf * 2]);  // Ah*Bl
                        mma16816(acc[mt][nt], a[1][mt], &b[0][bt][hf * 2]);  // Al*Bh
                    }
        }
        __syncthreads();
        buf = (buf + 1 == NSTAGE) ? 0 : buf + 1;
        nxt = (nxt + 1 == NSTAGE) ? 0 : nxt + 1;
    }

    // ---- epilogue ----
    const int g = lane >> 2, qd = lane & 3;
    #pragma unroll
    for (int mt = 0; mt < 2; mt++) {
        const int r0 = bm + wm + mt * 16 + g;
        #pragma unroll
        for (int nt = 0; nt < 8; nt++) {
            const int col = bn + wn + nt * 8 + qd * 2;
            #pragma unroll
            for (int half = 0; half < 2; half++) {
                const int row = r0 + half * 8;
                float x0 = acc[mt][nt][half * 2 + 0] * alpha;
                float x1 = acc[mt][nt][half * 2 + 1] * alpha;
                const size_t idx = (size_t)row * N + col;
                if (OutH) {
                    bf16 h0, l0, h1, l1;
                    split_bf(x0, h0, l0);
                    split_bf(x1, h1, l1);
                    *(uint32_t*)(OutH + idx) = pack_bf2(h0, h1);
                    *(uint32_t*)(OutL + idx) = pack_bf2(l0, l1);
                } else {
                    if (bias) { x0 += bias[col]; x1 += bias[col + 1]; }
                    if (addm) {
                        const float2 a2 = *(const float2*)&addm[idx];
                        x0 += a2.x; x1 += a2.y;
                    }
                    *(float2*)&Cf[idx] = make_float2(x0, x1);
                }
            }
        }
    }
}

// ===========================================================================
// Transpose + split: src fp32 [R,C] -> (dh,dl) bf16 [C,R]
// ===========================================================================
__global__ __launch_bounds__(256)
void transconv_kernel(const float* __restrict__ src, int R, int C,
                      bf16* __restrict__ dh, bf16* __restrict__ dl)
{
    __shared__ float t[32][33];
    const int c0 = blockIdx.x * 32, r0 = blockIdx.y * 32;
    const int tx = threadIdx.x & 31, ty = threadIdx.x >> 5;
    #pragma unroll
    for (int i = 0; i < 4; i++)
        t[ty + i * 8][tx] = src[(size_t)(r0 + ty + i * 8) * C + c0 + tx];
    __syncthreads();
    #pragma unroll
    for (int i = 0; i < 4; i++) {
        const float x = t[tx][ty + i * 8];
        bf16 h, l; split_bf(x, h, l);
        const size_t idx = (size_t)(c0 + ty + i * 8) * R + r0 + tx;
        dh[idx] = h; dl[idx] = l;
    }
}

// ===========================================================================
// Block reductions (256 threads)
// ===========================================================================
__device__ __forceinline__ float block_reduce_sum(float v) {
    __shared__ float red[8];
    const int lane = threadIdx.x & 31, wid = threadIdx.x >> 5;
    #pragma unroll
    for (int o = 16; o > 0; o >>= 1) v += __shfl_down_sync(0xffffffffu, v, o);
    __syncthreads();
    if (lane == 0) red[wid] = v;
    __syncthreads();
    float r = 0.f;
    if (threadIdx.x < 8) r = red[threadIdx.x];
    if (wid == 0) {
        #pragma unroll
        for (int o = 4; o > 0; o >>= 1) r += __shfl_down_sync(0xffu, r, o);
        if (lane == 0) red[0] = r;
    }
    __syncthreads();
    return red[0];
}
__device__ __forceinline__ float block_reduce_max(float v) {
    __shared__ float red[8];
    const int lane = threadIdx.x & 31, wid = threadIdx.x >> 5;
    #pragma unroll
    for (int o = 16; o > 0; o >>= 1) v = fmaxf(v, __shfl_down_sync(0xffffffffu, v, o));
    __syncthreads();
    if (lane == 0) red[wid] = v;
    __syncthreads();
    float r = -3.0e38f;
    if (threadIdx.x < 8) r = red[threadIdx.x];
    if (wid == 0) {
        #pragma unroll
        for (int o = 4; o > 0; o >>= 1) r = fmaxf(r, __shfl_down_sync(0xffu, r, o));
        if (lane == 0) red[0] = r;
    }
    __syncthreads();
    return red[0];
}

// ===========================================================================
// inv_freq table (512 entries)
// ===========================================================================
__global__ void init_invf_kernel(float* __restrict__ invf)
{
    const int j = threadIdx.x;                // 512 threads
    const float L2B = 13.28771237954945f;     // log2(10000)
    invf[j] = exp2f(-(float)j * (L2B / 512.0f));
}

// ===========================================================================
// RMSNorm -> split bf16 output. One block (256 thr) per row of 1024.
// ===========================================================================
__global__ __launch_bounds__(256)
void rmsnorm_bf_kernel(const float* __restrict__ x, const float* __restrict__ g,
                       bf16* __restrict__ oh, bf16* __restrict__ ol)
{
    const size_t row = blockIdx.x;
    const int i = threadIdx.x * 4;
    const float4 v = *(const float4*)&x[row * DD + i];
    float ss = v.x*v.x + v.y*v.y + v.z*v.z + v.w*v.w;
    ss = block_reduce_sum(ss);
    const float inv = rsqrtf(ss * (1.0f / DD) + EPSF);
    const float4 gg = *(const float4*)&g[i];
    const float o0 = v.x*inv*gg.x, o1 = v.y*inv*gg.y, o2 = v.z*inv*gg.z, o3 = v.w*inv*gg.w;
    bf16 h0,l0,h1,l1,h2,l2,h3,l3;
    split_bf(o0,h0,l0); split_bf(o1,h1,l1); split_bf(o2,h2,l2); split_bf(o3,h3,l3);
    const size_t idx = row * DD + i;
    *(uint2*)(oh + idx) = make_uint2(pack_bf2(h0,h1), pack_bf2(h2,h3));
    *(uint2*)(ol + idx) = make_uint2(pack_bf2(l0,l1), pack_bf2(l2,l3));
}

// ===========================================================================
// RoPE: read fp32, write split bf16. 512 pairs per row of 1024.
// ===========================================================================
__global__ __launch_bounds__(256)
void rope_bf_kernel(const float* __restrict__ x, const int* __restrict__ positions,
                    const float* __restrict__ invf,
                    bf16* __restrict__ oh, bf16* __restrict__ ol)
{
    const size_t row = blockIdx.x;
    const float p = (float)positions[row];
    const float* xr = x + row * DD;
    #pragma unroll
    for (int jj = 0; jj < 2; jj++) {
        const int j = threadIdx.x + jj * 256;
        float s, c;
        sincosf(p * __ldg(&invf[j]), &s, &c);
        const float x1 = xr[2*j], x2 = xr[2*j + 1];
        const float r1 = x1 * c - x2 * s;
        const float r2 = x1 * s + x2 * c;
        bf16 h1, l1, h2, l2;
        split_bf(r1, h1, l1); split_bf(r2, h2, l2);
        const size_t idx = row * DD + 2*j;
        *(uint32_t*)(oh + idx) = pack_bf2(h1, h2);
        *(uint32_t*)(ol + idx) = pack_bf2(l1, l2);
    }
}

// ===========================================================================
// Gumbel + softmax over C=1024; writes log_alpha_tau, z (fp32) and z split bf16.
// ===========================================================================
__global__ __launch_bounds__(256)
void gumbel_softmax_kernel(const float* __restrict__ la, const float* __restrict__ noise,
                           const float* __restrict__ tau_p, const float* __restrict__ gns_p,
                           float* __restrict__ lat_out, float* __restrict__ z_out,
                           bf16* __restrict__ zh, bf16* __restrict__ zl)
{
    const size_t row = blockIdx.x;
    const float inv_tau = 1.0f / (*tau_p);
    const float gns = *gns_p;
    const size_t base = row * CC + threadIdx.x * 4;

    const float4 la4 = *(const float4*)&la[base];
    const float4 u4  = *(const float4*)&noise[base];
    float lt[4];
    const float u[4] = {u4.x, u4.y, u4.z, u4.w};
    const float l[4] = {la4.x, la4.y, la4.z, la4.w};
    #pragma unroll
    for (int t = 0; t < 4; t++) {
        const float gum = -__logf(-__logf(u[t] + 1e-10f) + 1e-10f);
        lt[t] = (l[t] + gns * gum) * inv_tau;
    }
    *(float4*)&lat_out[base] = make_float4(lt[0], lt[1], lt[2], lt[3]);

    float m = fmaxf(fmaxf(lt[0], lt[1]), fmaxf(lt[2], lt[3]));
    m = block_reduce_max(m);
    float e[4], s = 0.f;
    #pragma unroll
    for (int t = 0; t < 4; t++) { e[t] = __expf(lt[t] - m); s += e[t]; }
    s = block_reduce_sum(s);
    const float invs = 1.0f / s;
    float z[4];
    #pragma unroll
    for (int t = 0; t < 4; t++) z[t] = e[t] * invs;
    *(float4*)&z_out[base] = make_float4(z[0], z[1], z[2], z[3]);
    bf16 h0,l0,h1,l1,h2,l2,h3,l3;
    split_bf(z[0],h0,l0); split_bf(z[1],h1,l1); split_bf(z[2],h2,l2); split_bf(z[3],h3,l3);
    *(uint2*)(zh + base) = make_uint2(pack_bf2(h0,h1), pack_bf2(h2,h3));
    *(uint2*)(zl + base) = make_uint2(pack_bf2(l0,l1), pack_bf2(l2,l3));
}

// ===========================================================================
// attn_out = rs*latents + y ; h = rmsnorm(attn_out)*g_ff -> split bf16.
// ===========================================================================
__global__ __launch_bounds__(256)
void residual_rms_kernel(const float* __restrict__ latents, const float* __restrict__ y,
                         const float* __restrict__ rs_p, const float* __restrict__ gff,
                         float* __restrict__ ao_out, bf16* __restrict__ hh, bf16* __restrict__ hl)
{
    const size_t row = blockIdx.x;
    const float rs = *rs_p;
    const size_t base = row * DD + threadIdx.x * 4;
    const float4 l4 = *(const float4*)&latents[base];
    const float4 y4 = *(const float4*)&y[base];
    float4 ao;
    ao.x = rs*l4.x + y4.x; ao.y = rs*l4.y + y4.y;
    ao.z = rs*l4.z + y4.z; ao.w = rs*l4.w + y4.w;
    *(float4*)&ao_out[base] = ao;
    float ss = ao.x*ao.x + ao.y*ao.y + ao.z*ao.z + ao.w*ao.w;
    ss = block_reduce_sum(ss);
    const float inv = rsqrtf(ss * (1.0f / DD) + EPSF);
    const float4 g4 = *(const float4*)&gff[threadIdx.x * 4];
    const float h0 = ao.x*inv*g4.x, h1 = ao.y*inv*g4.y, h2 = ao.z*inv*g4.z, h3 = ao.w*inv*g4.w;
    bf16 a0,b0,a1,b1,a2,b2,a3,b3;
    split_bf(h0,a0,b0); split_bf(h1,a1,b1); split_bf(h2,a2,b2); split_bf(h3,a3,b3);
    *(uint2*)(hh + base) = make_uint2(pack_bf2(a0,a1), pack_bf2(a2,a3));
    *(uint2*)(hl + base) = make_uint2(pack_bf2(b0,b1), pack_bf2(b2,b3));
}

// ===========================================================================
// prod = silu(t13[:, :HH]) * t13[:, HH:] -> split bf16 [MM, HH]
// One thread per 4 elements; grid sized exactly.
// ===========================================================================
__global__ __launch_bounds__(256)
void silu_mul_bf_kernel(const float* __restrict__ t13,
                        bf16* __restrict__ ph, bf16* __restrict__ pl)
{
    const size_t t = (size_t)blockIdx.x * 256 + threadIdx.x;   // over MM*HH/4
    const size_t row = t / (HH / 4);
    const size_t cq  = t % (HH / 4);
    const size_t src = row * HH2 + cq * 4;
    const float4 a = *(const float4*)&t13[src];
    const float4 b = *(const float4*)&t13[src + HH];
    float p[4];
    p[0] = (a.x / (1.0f + __expf(-a.x))) * b.x;
    p[1] = (a.y / (1.0f + __expf(-a.y))) * b.y;
    p[2] = (a.z / (1.0f + __expf(-a.z))) * b.z;
    p[3] = (a.w / (1.0f + __expf(-a.w))) * b.w;
    bf16 h0,l0,h1,l1,h2,l2,h3,l3;
    split_bf(p[0],h0,l0); split_bf(p[1],h1,l1); split_bf(p[2],h2,l2); split_bf(p[3],h3,l3);
    const size_t dst = row * HH + cq * 4;
    *(uint2*)(ph + dst) = make_uint2(pack_bf2(h0,h1), pack_bf2(h2,h3));
    *(uint2*)(pl + dst) = make_uint2(pack_bf2(l0,l1), pack_bf2(l2,l3));
}

// ===========================================================================
// Launch
// ===========================================================================
extern "C" void kernel_launch(void* const* d_in, const int* in_sizes, int n_in,
                              void* d_out, int out_size)
{
    (void)in_sizes; (void)n_in; (void)out_size;

    const float* latents  = (const float*)d_in[0];
    const float* codebook = (const float*)d_in[1];
    const float* Wq       = (const float*)d_in[2];
    const float* Wk       = (const float*)d_in[3];
    const float* Wv       = (const float*)d_in[4];
    const float* bv       = (const float*)d_in[5];
    const float* Wc       = (const float*)d_in[6];
    const float* w1       = (const float*)d_in[7];
    const float* w2       = (const float*)d_in[8];
    const float* w3       = (const float*)d_in[9];
    const float* gctx     = (const float*)d_in[10];
    const float* gq       = (const float*)d_in[11];
    const float* gff      = (const float*)d_in[12];
    const float* noise    = (const float*)d_in[13];
    const int*   positions= (const int*)d_in[14];
    const float* tau      = (const float*)d_in[15];
    const float* rs       = (const float*)d_in[16];
    const float* gns      = (const float*)d_in[17];

    cudaFuncSetAttribute(bf3_gemm, cudaFuncAttributeMaxDynamicSharedMemorySize, GEMM_SMEM_BYTES);

    #define SYM(v, s) do { void* _p; cudaGetSymbolAddress(&_p, s); v = (decltype(v))_p; } while (0)
    bf16 *wqT_h,*wqT_l,*wkT_h,*wkT_l,*wvT_h,*wvT_l,*wcT_h,*wcT_l;
    bf16 *w13T_h,*w13T_l,*w2T_h,*w2T_l;
    bf16 *nctx_h,*nctx_l,*k_h,*k_l,*vT_h,*vT_l,*nq_h,*nq_l,*q_h,*q_l;
    bf16 *z_h,*z_l,*attn_h,*attn_l,*h_h,*h_l,*p_h,*p_l;
    float *kf,*vf,*qf,*yf,*ao,*t13,*invf;
    SYM(wqT_h,g_wqT_h); SYM(wqT_l,g_wqT_l); SYM(wkT_h,g_wkT_h); SYM(wkT_l,g_wkT_l);
    SYM(wvT_h,g_wvT_h); SYM(wvT_l,g_wvT_l); SYM(wcT_h,g_wcT_h); SYM(wcT_l,g_wcT_l);
    SYM(w13T_h,g_w13T_h); SYM(w13T_l,g_w13T_l);
    SYM(w2T_h,g_w2T_h); SYM(w2T_l,g_w2T_l);
    SYM(nctx_h,g_nctx_h); SYM(nctx_l,g_nctx_l);
    SYM(k_h,g_k_h); SYM(k_l,g_k_l); SYM(vT_h,g_vT_h); SYM(vT_l,g_vT_l);
    SYM(nq_h,g_nq_h); SYM(nq_l,g_nq_l); SYM(q_h,g_q_h); SYM(q_l,g_q_l);
    SYM(z_h,g_z_h); SYM(z_l,g_z_l); SYM(attn_h,g_attn_h); SYM(attn_l,g_attn_l);
    SYM(h_h,g_h_h); SYM(h_l,g_h_l); SYM(p_h,g_p_h); SYM(p_l,g_p_l);
    SYM(kf,g_kf); SYM(vf,g_vf); SYM(qf,g_qf); SYM(yf,g_yf); SYM(ao,g_ao);
    SYM(t13,g_t13); SYM(invf,g_invf);
    #undef SYM

    float* out_cb  = (float*)d_out;
    float* out_la  = out_cb  + (size_t)MM * DD;
    float* out_lat = out_la  + (size_t)MM * CC;
    float* out_z   = out_lat + (size_t)MM * CC;

    const float inv_scale = 1.0f / 32.0f;   // 1/sqrt(1024)

    // Launch order chosen so launch #6 (ncu: -s 5 -c 1) is the Wq GEMM.
    init_invf_kernel<<<1, 512>>>(invf);                               // 1
    rmsnorm_bf_kernel<<<CC, 256>>>(codebook, gctx, nctx_h, nctx_l);   // 2
    rmsnorm_bf_kernel<<<MM, 256>>>(latents, gq, nq_h, nq_l);          // 3
    transconv_kernel<<<dim3(DD/32, DD/32), 256>>>(Wq, DD, DD, wqT_h, wqT_l);   // 4
    transconv_kernel<<<dim3(DD/32, DD/32), 256>>>(Wk, DD, DD, wkT_h, wkT_l);   // 5
    bf3_gemm<<<dim3(DD/128, MM/128), 256, GEMM_SMEM_BYTES>>>(                   // 6 (PROFILED)
        nq_h, nq_l, wqT_h, wqT_l, qf, nullptr, nullptr, MM, DD, DD, 1.f, nullptr, nullptr);

    transconv_kernel<<<dim3(DD/32, DD/32), 256>>>(Wv, DD, DD, wvT_h, wvT_l);
    transconv_kernel<<<dim3(DD/32, DD/32), 256>>>(Wc, DD, DD, wcT_h, wcT_l);
    transconv_kernel<<<dim3(HH/32, DD/32), 256>>>(w1, DD, HH, w13T_h, w13T_l);
    transconv_kernel<<<dim3(HH/32, DD/32), 256>>>(w3, DD, HH,
        w13T_h + (size_t)HH*DD, w13T_l + (size_t)HH*DD);
    transconv_kernel<<<dim3(DD/32, HH/32), 256>>>(w2, HH, DD, w2T_h, w2T_l);

    // --- context path ---
    bf3_gemm<<<dim3(DD/128, CC/128), 256, GEMM_SMEM_BYTES>>>(
        nctx_h, nctx_l, wkT_h, wkT_l, kf, nullptr, nullptr, CC, DD, DD, 1.f, nullptr, nullptr);
    bf3_gemm<<<dim3(DD/128, CC/128), 256, GEMM_SMEM_BYTES>>>(
        nctx_h, nctx_l, wvT_h, wvT_l, vf, nullptr, nullptr, CC, DD, DD, 1.f, bv, nullptr);
    rope_bf_kernel<<<CC, 256>>>(kf, positions, invf, k_h, k_l);
    transconv_kernel<<<dim3(DD/32, CC/32), 256>>>(vf, CC, DD, vT_h, vT_l);

    // --- query path ---
    rope_bf_kernel<<<MM, 256>>>(qf, positions, invf, q_h, q_l);

    // log_alpha = q @ k^T / 32
    bf3_gemm<<<dim3(CC/128, MM/128), 256, GEMM_SMEM_BYTES>>>(
        q_h, q_l, k_h, k_l, out_la, nullptr, nullptr, MM, CC, DD, inv_scale, nullptr, nullptr);

    // gumbel + softmax
    gumbel_softmax_kernel<<<MM, 256>>>(out_la, noise, tau, gns, out_lat, out_z, z_h, z_l);

    // attn = z @ v (split bf16 out) ; y = attn @ Wc
    bf3_gemm<<<dim3(DD/128, MM/128), 256, GEMM_SMEM_BYTES>>>(
        z_h, z_l, vT_h, vT_l, nullptr, attn_h, attn_l, MM, DD, CC, 1.f, nullptr, nullptr);
    bf3_gemm<<<dim3(DD/128, MM/128), 256, GEMM_SMEM_BYTES>>>(
        attn_h, attn_l, wcT_h, wcT_l, yf, nullptr, nullptr, MM, DD, DD, 1.f, nullptr, nullptr);

    // residual + rmsnorm
    residual_rms_kernel<<<MM, 256>>>(latents, yf, rs, gff, ao, h_h, h_l);

    // FFN (fused w1|w3)
    bf3_gemm<<<dim3(HH2/128, MM/128), 256, GEMM_SMEM_BYTES>>>(
        h_h, h_l, w13T_h, w13T_l, t13, nullptr, nullptr, MM, HH2, DD, 1.f, nullptr, nullptr);
    silu_mul_bf_kernel<<<(unsigned)((size_t)MM * HH / 4 / 256), 256>>>(t13, p_h, p_l);
    bf3_gemm<<<dim3(DD/128, MM/128), 256, GEMM_SMEM_BYTES>>>(
        p_h, p_l, w2T_h, w2T_l, out_cb, nullptr, nullptr, MM, DD, HH, 1.f, nullptr, ao);
}

// round 8
// speedup vs baseline: 6.9357x; 1.3676x over previous
#include <cuda_runtime.h>
#include <cuda_fp16.h>
#include <cstdint>
#include <cstddef>

// Problem constants
#define BB 8
#define NN 2048
#define DD 1024
#define CC 1024
#define HH 4096
#define HH2 (2*HH)          // fused w1|w3 output width
#define MM (BB*NN)          // 16384
#define EPSF 1e-6f

typedef __half fp16;

// ===========================================================================
// Helpers
// ===========================================================================
__device__ __forceinline__ uint32_t smem_u32(const void* p) {
    uint32_t a;
    asm("{ .reg .u64 t; cvta.to.shared.u64 t, %1; cvt.u32.u64 %0, t; }" : "=r"(a) : "l"(p));
    return a;
}
__device__ __forceinline__ void ldsm4(uint32_t* r, uint32_t addr) {
    asm volatile("ldmatrix.sync.aligned.m8n8.x4.shared.b16 {%0,%1,%2,%3}, [%4];"
        : "=r"(r[0]), "=r"(r[1]), "=r"(r[2]), "=r"(r[3]) : "r"(addr));
}
__device__ __forceinline__ void mma16816(float* d, const uint32_t* a, const uint32_t* b) {
    asm volatile("mma.sync.aligned.m16n8k16.row.col.f32.f16.f16.f32 "
        "{%0,%1,%2,%3}, {%4,%5,%6,%7}, {%8,%9}, {%0,%1,%2,%3};"
        : "+f"(d[0]), "+f"(d[1]), "+f"(d[2]), "+f"(d[3])
        : "r"(a[0]), "r"(a[1]), "r"(a[2]), "r"(a[3]), "r"(b[0]), "r"(b[1]));
}
__device__ __forceinline__ void cp_async16(uint32_t dst, const void* src) {
    asm volatile("cp.async.cg.shared.global [%0], [%1], 16;"
        :: "r"(dst), "l"(__cvta_generic_to_global(src)));
}
#define CP_COMMIT()  asm volatile("cp.async.commit_group;" ::: "memory")
#define CP_WAIT(n)   asm volatile("cp.async.wait_group %0;" :: "n"(n) : "memory")

__device__ __forceinline__ void split_h(float x, fp16& h, fp16& l) {
    h = __float2half_rn(x);
    l = __float2half_rn(x - __half2float(h));
}
__device__ __forceinline__ uint32_t pack_h2(fp16 a, fp16 b) {
    __half2 p; p.x = a; p.y = b;
    return *(uint32_t*)&p;
}

// ===========================================================================
// Scratch (device globals)
// ===========================================================================
// Weights (transposed, single fp16)
__device__ __align__(16) fp16 g_wqT[DD*DD];
__device__ __align__(16) fp16 g_wkT[DD*DD];
__device__ __align__(16) fp16 g_wvT[DD*DD];
__device__ __align__(16) fp16 g_wcT[DD*DD];
__device__ __align__(16) fp16 g_w13T[(size_t)HH2*DD];
__device__ __align__(16) fp16 g_w2T[(size_t)DD*HH];
// Context
__device__ __align__(16) fp16 g_nctx_h[CC*DD], g_nctx_l[CC*DD];
__device__ float g_kf[CC*DD];
__device__ float g_vf[CC*DD];
__device__ __align__(16) fp16 g_k[CC*DD];          // single fp16 (B operand)
__device__ __align__(16) fp16 g_vT[DD*CC];         // single fp16 (B operand)
// Query path (A operands: split)
__device__ __align__(16) fp16 g_nq_h[(size_t)MM*DD], g_nq_l[(size_t)MM*DD];
__device__ float g_qf[(size_t)MM*DD];
__device__ __align__(16) fp16 g_q_h[(size_t)MM*DD], g_q_l[(size_t)MM*DD];
__device__ __align__(16) fp16 g_z_h[(size_t)MM*CC], g_z_l[(size_t)MM*CC];
__device__ __align__(16) fp16 g_attn_h[(size_t)MM*DD], g_attn_l[(size_t)MM*DD];
__device__ float g_yf[(size_t)MM*DD];
__device__ float g_ao[(size_t)MM*DD];
__device__ __align__(16) fp16 g_h_h[(size_t)MM*DD], g_h_l[(size_t)MM*DD];
__device__ float g_t13[(size_t)MM*HH2];
__device__ __align__(16) fp16 g_p_h[(size_t)MM*HH], g_p_l[(size_t)MM*HH];
__device__ float g_invf[512];

// ===========================================================================
// fp16 2-MMA split GEMM: C[M,N] = alpha*(Ah+Al)@B^T (+bias)(+addm)
//   A = (Ah,Al) [M,K] fp16 row-major (double-split); B [N,K] fp16 row-major.
//   If OutH != nullptr: write split fp16 (OutH,OutL) instead of fp32 C.
// 256 threads, CTA tile 128x128, BK=32, 3-stage cp.async pipeline.
// SMEM tile pitch = 40 fp16 (80 B) -> conflict-free ldmatrix.
// ===========================================================================
#define TILE_ELEMS (128 * 40)                  // 5120 fp16 = 10240 B
#define STAGE_ELEMS (3 * TILE_ELEMS)           // Ah, Al, B
#define STAGE_BYTES (STAGE_ELEMS * 2)          // 30720 B
#define NSTAGE 3
#define GEMM_SMEM_BYTES (NSTAGE * STAGE_BYTES) // 92160 B

__device__ __forceinline__ void stage_load(
    uint32_t sm_stage, const fp16* __restrict__ Ah, const fp16* __restrict__ Al,
    const fp16* __restrict__ B, int bm, int bn, int K, int k0, int tid)
{
    #pragma unroll
    for (int t = 0; t < 3; t++) {
        const fp16* gb = (t == 0) ? Ah : (t == 1) ? Al : B;
        const int brow = (t < 2) ? bm : bn;
        gb += (size_t)brow * K + k0;
        const uint32_t sb = sm_stage + t * (TILE_ELEMS * 2);
        #pragma unroll
        for (int j = 0; j < 2; j++) {
            const int c = tid + j * 256;
            const int row = c >> 2, ch = c & 3;
            cp_async16(sb + row * 80 + ch * 16, gb + (size_t)row * K + ch * 8);
        }
    }
}

__global__ __launch_bounds__(256, 1)
void fp16_gemm(const fp16* __restrict__ Ah, const fp16* __restrict__ Al,
               const fp16* __restrict__ B,
               float* __restrict__ Cf, fp16* __restrict__ OutH, fp16* __restrict__ OutL,
               int M, int N, int K, float alpha,
               const float* __restrict__ bias, const float* __restrict__ addm)
{
    extern __shared__ char smem[];
    const uint32_t sb = smem_u32(smem);
    const int tid = threadIdx.x, wid = tid >> 5, lane = tid & 31;
    const int bm = blockIdx.y * 128, bn = blockIdx.x * 128;
    const int wm = (wid >> 1) * 32, wn = (wid & 1) * 64;

    float acc[2][8][4];
    #pragma unroll
    for (int i = 0; i < 2; i++)
        #pragma unroll
        for (int j = 0; j < 8; j++)
            #pragma unroll
            for (int q = 0; q < 4; q++) acc[i][j][q] = 0.f;

    const uint32_t aoff = (uint32_t)((wm + (lane & 15)) * 80 + (lane >> 4) * 16);
    const uint32_t boff = (uint32_t)((wn + (lane & 7) + ((lane >> 4) & 1) * 8) * 80
                                     + ((lane >> 3) & 1) * 16);

    const int S = K >> 5;   // K/32 stages (>= 32 for all our GEMMs)
    stage_load(sb, Ah, Al, B, bm, bn, K, 0, tid);
    CP_COMMIT();
    stage_load(sb + STAGE_BYTES, Ah, Al, B, bm, bn, K, 32, tid);
    CP_COMMIT();

    int buf = 0;
    int nxt = 2 % NSTAGE;
    for (int s = 0; s < S; s++) {
        if (s + 2 < S)
            stage_load(sb + nxt * STAGE_BYTES, Ah, Al, B, bm, bn, K, (s + 2) << 5, tid);
        CP_COMMIT();
        CP_WAIT(2);
        __syncthreads();

        const uint32_t stg = sb + buf * STAGE_BYTES;
        const uint32_t tAh = stg;
        const uint32_t tAl = stg + TILE_ELEMS * 2;
        const uint32_t tB  = stg + 2 * TILE_ELEMS * 2;

        #pragma unroll
        for (int ks = 0; ks < 2; ks++) {
            const uint32_t ko = ks * 32;
            uint32_t a[2][2][4];   // [split][mt]
            uint32_t b[4][4];      // [bt]
            #pragma unroll
            for (int mt = 0; mt < 2; mt++) {
                ldsm4(a[0][mt], tAh + aoff + mt * (16 * 80) + ko);
                ldsm4(a[1][mt], tAl + aoff + mt * (16 * 80) + ko);
            }
            #pragma unroll
            for (int bt = 0; bt < 4; bt++)
                ldsm4(b[bt], tB + boff + bt * (16 * 80) + ko);
            #pragma unroll
            for (int mt = 0; mt < 2; mt++)
                #pragma unroll
                for (int bt = 0; bt < 4; bt++)
                    #pragma unroll
                    for (int hf = 0; hf < 2; hf++) {
                        const int nt = bt * 2 + hf;
                        mma16816(acc[mt][nt], a[0][mt], &b[bt][hf * 2]);  // Ah*B
                        mma16816(acc[mt][nt], a[1][mt], &b[bt][hf * 2]);  // Al*B
                    }
        }
        __syncthreads();
        buf = (buf + 1 == NSTAGE) ? 0 : buf + 1;
        nxt = (nxt + 1 == NSTAGE) ? 0 : nxt + 1;
    }

    // ---- epilogue ----
    const int g = lane >> 2, qd = lane & 3;
    #pragma unroll
    for (int mt = 0; mt < 2; mt++) {
        const int r0 = bm + wm + mt * 16 + g;
        #pragma unroll
        for (int nt = 0; nt < 8; nt++) {
            const int col = bn + wn + nt * 8 + qd * 2;
            #pragma unroll
            for (int half = 0; half < 2; half++) {
                const int row = r0 + half * 8;
                float x0 = acc[mt][nt][half * 2 + 0] * alpha;
                float x1 = acc[mt][nt][half * 2 + 1] * alpha;
                const size_t idx = (size_t)row * N + col;
                if (OutH) {
                    fp16 h0, l0, h1, l1;
                    split_h(x0, h0, l0);
                    split_h(x1, h1, l1);
                    *(uint32_t*)(OutH + idx) = pack_h2(h0, h1);
                    *(uint32_t*)(OutL + idx) = pack_h2(l0, l1);
                } else {
                    if (bias) { x0 += bias[col]; x1 += bias[col + 1]; }
                    if (addm) {
                        const float2 a2 = *(const float2*)&addm[idx];
                        x0 += a2.x; x1 += a2.y;
                    }
                    *(float2*)&Cf[idx] = make_float2(x0, x1);
                }
            }
        }
    }
}

// ===========================================================================
// Transpose + convert: src fp32 [R,C] -> dst fp16 [C,R] (single, round-nearest)
// ===========================================================================
__global__ __launch_bounds__(256)
void transconv_kernel(const float* __restrict__ src, int R, int C,
                      fp16* __restrict__ dst)
{
    __shared__ float t[32][33];
    const int c0 = blockIdx.x * 32, r0 = blockIdx.y * 32;
    const int tx = threadIdx.x & 31, ty = threadIdx.x >> 5;
    #pragma unroll
    for (int i = 0; i < 4; i++)
        t[ty + i * 8][tx] = src[(size_t)(r0 + ty + i * 8) * C + c0 + tx];
    __syncthreads();
    #pragma unroll
    for (int i = 0; i < 4; i++) {
        const float x = t[tx][ty + i * 8];
        dst[(size_t)(c0 + ty + i * 8) * R + r0 + tx] = __float2half_rn(x);
    }
}

// ===========================================================================
// Block reductions (256 threads)
// ===========================================================================
__device__ __forceinline__ float block_reduce_sum(float v) {
    __shared__ float red[8];
    const int lane = threadIdx.x & 31, wid = threadIdx.x >> 5;
    #pragma unroll
    for (int o = 16; o > 0; o >>= 1) v += __shfl_down_sync(0xffffffffu, v, o);
    __syncthreads();
    if (lane == 0) red[wid] = v;
    __syncthreads();
    float r = 0.f;
    if (threadIdx.x < 8) r = red[threadIdx.x];
    if (wid == 0) {
        #pragma unroll
        for (int o = 4; o > 0; o >>= 1) r += __shfl_down_sync(0xffu, r, o);
        if (lane == 0) red[0] = r;
    }
    __syncthreads();
    return red[0];
}
__device__ __forceinline__ float block_reduce_max(float v) {
    __shared__ float red[8];
    const int lane = threadIdx.x & 31, wid = threadIdx.x >> 5;
    #pragma unroll
    for (int o = 16; o > 0; o >>= 1) v = fmaxf(v, __shfl_down_sync(0xffffffffu, v, o));
    __syncthreads();
    if (lane == 0) red[wid] = v;
    __syncthreads();
    float r = -3.0e38f;
    if (threadIdx.x < 8) r = red[threadIdx.x];
    if (wid == 0) {
        #pragma unroll
        for (int o = 4; o > 0; o >>= 1) r = fmaxf(r, __shfl_down_sync(0xffu, r, o));
        if (lane == 0) red[0] = r;
    }
    __syncthreads();
    return red[0];
}

// ===========================================================================
// inv_freq table (512 entries)
// ===========================================================================
__global__ void init_invf_kernel(float* __restrict__ invf)
{
    const int j = threadIdx.x;                // 512 threads
    const float L2B = 13.28771237954945f;     // log2(10000)
    invf[j] = exp2f(-(float)j * (L2B / 512.0f));
}

// ===========================================================================
// RMSNorm -> split fp16 output. One block (256 thr) per row of 1024.
// ===========================================================================
__global__ __launch_bounds__(256)
void rmsnorm_h_kernel(const float* __restrict__ x, const float* __restrict__ g,
                      fp16* __restrict__ oh, fp16* __restrict__ ol)
{
    const size_t row = blockIdx.x;
    const int i = threadIdx.x * 4;
    const float4 v = *(const float4*)&x[row * DD + i];
    float ss = v.x*v.x + v.y*v.y + v.z*v.z + v.w*v.w;
    ss = block_reduce_sum(ss);
    const float inv = rsqrtf(ss * (1.0f / DD) + EPSF);
    const float4 gg = *(const float4*)&g[i];
    const float o0 = v.x*inv*gg.x, o1 = v.y*inv*gg.y, o2 = v.z*inv*gg.z, o3 = v.w*inv*gg.w;
    fp16 h0,l0,h1,l1,h2,l2,h3,l3;
    split_h(o0,h0,l0); split_h(o1,h1,l1); split_h(o2,h2,l2); split_h(o3,h3,l3);
    const size_t idx = row * DD + i;
    *(uint2*)(oh + idx) = make_uint2(pack_h2(h0,h1), pack_h2(h2,h3));
    *(uint2*)(ol + idx) = make_uint2(pack_h2(l0,l1), pack_h2(l2,l3));
}

// ===========================================================================
// RoPE: read fp32, write split fp16 (ol != null) or single fp16 (ol == null).
// ===========================================================================
__global__ __launch_bounds__(256)
void rope_h_kernel(const float* __restrict__ x, const int* __restrict__ positions,
                   const float* __restrict__ invf,
                   fp16* __restrict__ oh, fp16* __restrict__ ol)
{
    const size_t row = blockIdx.x;
    const float p = (float)positions[row];
    const float* xr = x + row * DD;
    #pragma unroll
    for (int jj = 0; jj < 2; jj++) {
        const int j = threadIdx.x + jj * 256;
        float s, c;
        sincosf(p * __ldg(&invf[j]), &s, &c);
        const float x1 = xr[2*j], x2 = xr[2*j + 1];
        const float r1 = x1 * c - x2 * s;
        const float r2 = x1 * s + x2 * c;
        const size_t idx = row * DD + 2*j;
        if (ol) {
            fp16 h1, l1, h2, l2;
            split_h(r1, h1, l1); split_h(r2, h2, l2);
            *(uint32_t*)(oh + idx) = pack_h2(h1, h2);
            *(uint32_t*)(ol + idx) = pack_h2(l1, l2);
        } else {
            *(uint32_t*)(oh + idx) = pack_h2(__float2half_rn(r1), __float2half_rn(r2));
        }
    }
}

// ===========================================================================
// Gumbel + softmax over C=1024; writes log_alpha_tau, z (fp32) and z split fp16.
// Precise logf (fast __logf corrupts u -> 1 tail); fast __expf is safe.
// ===========================================================================
__global__ __launch_bounds__(256)
void gumbel_softmax_kernel(const float* __restrict__ la, const float* __restrict__ noise,
                           const float* __restrict__ tau_p, const float* __restrict__ gns_p,
                           float* __restrict__ lat_out, float* __restrict__ z_out,
                           fp16* __restrict__ zh, fp16* __restrict__ zl)
{
    const size_t row = blockIdx.x;
    const float inv_tau = 1.0f / (*tau_p);
    const float gns = *gns_p;
    const size_t base = row * CC + threadIdx.x * 4;

    const float4 la4 = *(const float4*)&la[base];
    const float4 u4  = *(const float4*)&noise[base];
    float lt[4];
    const float u[4] = {u4.x, u4.y, u4.z, u4.w};
    const float l[4] = {la4.x, la4.y, la4.z, la4.w};
    #pragma unroll
    for (int t = 0; t < 4; t++) {
        const float gum = -logf(-logf(u[t] + 1e-10f) + 1e-10f);
        lt[t] = (l[t] + gns * gum) * inv_tau;
    }
    *(float4*)&lat_out[base] = make_float4(lt[0], lt[1], lt[2], lt[3]);

    float m = fmaxf(fmaxf(lt[0], lt[1]), fmaxf(lt[2], lt[3]));
    m = block_reduce_max(m);
    float e[4], s = 0.f;
    #pragma unroll
    for (int t = 0; t < 4; t++) { e[t] = __expf(lt[t] - m); s += e[t]; }
    s = block_reduce_sum(s);
    const float invs = 1.0f / s;
    float z[4];
    #pragma unroll
    for (int t = 0; t < 4; t++) z[t] = e[t] * invs;
    *(float4*)&z_out[base] = make_float4(z[0], z[1], z[2], z[3]);
    fp16 h0,l0,h1,l1,h2,l2,h3,l3;
    split_h(z[0],h0,l0); split_h(z[1],h1,l1); split_h(z[2],h2,l2); split_h(z[3],h3,l3);
    *(uint2*)(zh + base) = make_uint2(pack_h2(h0,h1), pack_h2(h2,h3));
    *(uint2*)(zl + base) = make_uint2(pack_h2(l0,l1), pack_h2(l2,l3));
}

// ===========================================================================
// attn_out = rs*latents + y ; h = rmsnorm(attn_out)*g_ff -> split fp16.
// ===========================================================================
__global__ __launch_bounds__(256)
void residual_rms_kernel(const float* __restrict__ latents, const float* __restrict__ y,
                         const float* __restrict__ rs_p, const float* __restrict__ gff,
                         float* __restrict__ ao_out, fp16* __restrict__ hh, fp16* __restrict__ hl)
{
    const size_t row = blockIdx.x;
    const float rs = *rs_p;
    const size_t base = row * DD + threadIdx.x * 4;
    const float4 l4 = *(const float4*)&latents[base];
    const float4 y4 = *(const float4*)&y[base];
    float4 ao;
    ao.x = rs*l4.x + y4.x; ao.y = rs*l4.y + y4.y;
    ao.z = rs*l4.z + y4.z; ao.w = rs*l4.w + y4.w;
    *(float4*)&ao_out[base] = ao;
    float ss = ao.x*ao.x + ao.y*ao.y + ao.z*ao.z + ao.w*ao.w;
    ss = block_reduce_sum(ss);
    const float inv = rsqrtf(ss * (1.0f / DD) + EPSF);
    const float4 g4 = *(const float4*)&gff[threadIdx.x * 4];
    const float h0 = ao.x*inv*g4.x, h1 = ao.y*inv*g4.y, h2 = ao.z*inv*g4.z, h3 = ao.w*inv*g4.w;
    fp16 a0,b0,a1,b1,a2,b2,a3,b3;
    split_h(h0,a0,b0); split_h(h1,a1,b1); split_h(h2,a2,b2); split_h(h3,a3,b3);
    *(uint2*)(hh + base) = make_uint2(pack_h2(a0,a1), pack_h2(a2,a3));
    *(uint2*)(hl + base) = make_uint2(pack_h2(b0,b1), pack_h2(b2,b3));
}

// ===========================================================================
// prod = silu(t13[:, :HH]) * t13[:, HH:] -> split fp16 [MM, HH]
// ===========================================================================
__global__ __launch_bounds__(256)
void silu_mul_h_kernel(const float* __restrict__ t13,
                       fp16* __restrict__ ph, fp16* __restrict__ pl)
{
    const size_t t = (size_t)blockIdx.x * 256 + threadIdx.x;   // over MM*HH/4
    const size_t row = t / (HH / 4);
    const size_t cq  = t % (HH / 4);
    const size_t src = row * HH2 + cq * 4;
    const float4 a = *(const float4*)&t13[src];
    const float4 b = *(const float4*)&t13[src + HH];
    float p[4];
    p[0] = (a.x / (1.0f + __expf(-a.x))) * b.x;
    p[1] = (a.y / (1.0f + __expf(-a.y))) * b.y;
    p[2] = (a.z / (1.0f + __expf(-a.z))) * b.z;
    p[3] = (a.w / (1.0f + __expf(-a.w))) * b.w;
    fp16 h0,l0,h1,l1,h2,l2,h3,l3;
    split_h(p[0],h0,l0); split_h(p[1],h1,l1); split_h(p[2],h2,l2); split_h(p[3],h3,l3);
    const size_t dst = row * HH + cq * 4;
    *(uint2*)(ph + dst) = make_uint2(pack_h2(h0,h1), pack_h2(h2,h3));
    *(uint2*)(pl + dst) = make_uint2(pack_h2(l0,l1), pack_h2(l2,l3));
}

// ===========================================================================
// Launch
// ===========================================================================
extern "C" void kernel_launch(void* const* d_in, const int* in_sizes, int n_in,
                              void* d_out, int out_size)
{
    (void)in_sizes; (void)n_in; (void)out_size;

    const float* latents  = (const float*)d_in[0];
    const float* codebook = (const float*)d_in[1];
    const float* Wq       = (const float*)d_in[2];
    const float* Wk       = (const float*)d_in[3];
    const float* Wv       = (const float*)d_in[4];
    const float* bv       = (const float*)d_in[5];
    const float* Wc       = (const float*)d_in[6];
    const float* w1       = (const float*)d_in[7];
    const float* w2       = (const float*)d_in[8];
    const float* w3       = (const float*)d_in[9];
    const float* gctx     = (const float*)d_in[10];
    const float* gq       = (const float*)d_in[11];
    const float* gff      = (const float*)d_in[12];
    const float* noise    = (const float*)d_in[13];
    const int*   positions= (const int*)d_in[14];
    const float* tau      = (const float*)d_in[15];
    const float* rs       = (const float*)d_in[16];
    const float* gns      = (const float*)d_in[17];

    cudaFuncSetAttribute(fp16_gemm, cudaFuncAttributeMaxDynamicSharedMemorySize, GEMM_SMEM_BYTES);

    #define SYM(v, s) do { void* _p; cudaGetSymbolAddress(&_p, s); v = (decltype(v))_p; } while (0)
    fp16 *wqT,*wkT,*wvT,*wcT,*w13T,*w2T;
    fp16 *nctx_h,*nctx_l,*k1,*vT,*nq_h,*nq_l,*q_h,*q_l;
    fp16 *z_h,*z_l,*attn_h,*attn_l,*h_h,*h_l,*p_h,*p_l;
    float *kf,*vf,*qf,*yf,*ao,*t13,*invf;
    SYM(wqT,g_wqT); SYM(wkT,g_wkT); SYM(wvT,g_wvT); SYM(wcT,g_wcT);
    SYM(w13T,g_w13T); SYM(w2T,g_w2T);
    SYM(nctx_h,g_nctx_h); SYM(nctx_l,g_nctx_l);
    SYM(k1,g_k); SYM(vT,g_vT);
    SYM(nq_h,g_nq_h); SYM(nq_l,g_nq_l); SYM(q_h,g_q_h); SYM(q_l,g_q_l);
    SYM(z_h,g_z_h); SYM(z_l,g_z_l); SYM(attn_h,g_attn_h); SYM(attn_l,g_attn_l);
    SYM(h_h,g_h_h); SYM(h_l,g_h_l); SYM(p_h,g_p_h); SYM(p_l,g_p_l);
    SYM(kf,g_kf); SYM(vf,g_vf); SYM(qf,g_qf); SYM(yf,g_yf); SYM(ao,g_ao);
    SYM(t13,g_t13); SYM(invf,g_invf);
    #undef SYM

    float* out_cb  = (float*)d_out;
    float* out_la  = out_cb  + (size_t)MM * DD;
    float* out_lat = out_la  + (size_t)MM * CC;
    float* out_z   = out_lat + (size_t)MM * CC;

    const float inv_scale = 1.0f / 32.0f;   // 1/sqrt(1024)

    // Launch order: #6 (ncu -s 5 -c 1) is the big Wq GEMM.
    init_invf_kernel<<<1, 512>>>(invf);                               // 1
    rmsnorm_h_kernel<<<CC, 256>>>(codebook, gctx, nctx_h, nctx_l);    // 2
    rmsnorm_h_kernel<<<MM, 256>>>(latents, gq, nq_h, nq_l);           // 3
    transconv_kernel<<<dim3(DD/32, DD/32), 256>>>(Wq, DD, DD, wqT);   // 4
    transconv_kernel<<<dim3(DD/32, DD/32), 256>>>(Wk, DD, DD, wkT);   // 5
    fp16_gemm<<<dim3(DD/128, MM/128), 256, GEMM_SMEM_BYTES>>>(         // 6 (PROFILED)
        nq_h, nq_l, wqT, qf, nullptr, nullptr, MM, DD, DD, 1.f, nullptr, nullptr);

    transconv_kernel<<<dim3(DD/32, DD/32), 256>>>(Wv, DD, DD, wvT);
    transconv_kernel<<<dim3(DD/32, DD/32), 256>>>(Wc, DD, DD, wcT);
    transconv_kernel<<<dim3(HH/32, DD/32), 256>>>(w1, DD, HH, w13T);
    transconv_kernel<<<dim3(HH/32, DD/32), 256>>>(w3, DD, HH, w13T + (size_t)HH*DD);
    transconv_kernel<<<dim3(DD/32, HH/32), 256>>>(w2, HH, DD, w2T);

    // --- context path ---
    fp16_gemm<<<dim3(DD/128, CC/128), 256, GEMM_SMEM_BYTES>>>(
        nctx_h, nctx_l, wkT, kf, nullptr, nullptr, CC, DD, DD, 1.f, nullptr, nullptr);
    fp16_gemm<<<dim3(DD/128, CC/128), 256, GEMM_SMEM_BYTES>>>(
        nctx_h, nctx_l, wvT, vf, nullptr, nullptr, CC, DD, DD, 1.f, bv, nullptr);
    rope_h_kernel<<<CC, 256>>>(kf, positions, invf, k1, nullptr);     // k single fp16
    transconv_kernel<<<dim3(DD/32, CC/32), 256>>>(vf, CC, DD, vT);    // vT single fp16

    // --- query path ---
    rope_h_kernel<<<MM, 256>>>(qf, positions, invf, q_h, q_l);        // q split

    // log_alpha = q @ k^T / 32
    fp16_gemm<<<dim3(CC/128, MM/128), 256, GEMM_SMEM_BYTES>>>(
        q_h, q_l, k1, out_la, nullptr, nullptr, MM, CC, DD, inv_scale, nullptr, nullptr);

    // gumbel + softmax
    gumbel_softmax_kernel<<<MM, 256>>>(out_la, noise, tau, gns, out_lat, out_z, z_h, z_l);

    // attn = z @ v (split fp16 out) ; y = attn @ Wc
    fp16_gemm<<<dim3(DD/128, MM/128), 256, GEMM_SMEM_BYTES>>>(
        z_h, z_l, vT, nullptr, attn_h, attn_l, MM, DD, CC, 1.f, nullptr, nullptr);
    fp16_gemm<<<dim3(DD/128, MM/128), 256, GEMM_SMEM_BYTES>>>(
        attn_h, attn_l, wcT, yf, nullptr, nullptr, MM, DD, DD, 1.f, nullptr, nullptr);

    // residual + rmsnorm
    residual_rms_kernel<<<MM, 256>>>(latents, yf, rs, gff, ao, h_h, h_l);

    // FFN (fused w1|w3)
    fp16_gemm<<<dim3(HH2/128, MM/128), 256, GEMM_SMEM_BYTES>>>(
        h_h, h_l, w13T, t13, nullptr, nullptr, MM, HH2, DD, 1.f, nullptr, nullptr);
    silu_mul_h_kernel<<<(unsigned)((size_t)MM * HH / 4 / 256), 256>>>(t13, p_h, p_l);
    fp16_gemm<<<dim3(DD/128, MM/128), 256, GEMM_SMEM_BYTES>>>(
        p_h, p_l, w2T, out_cb, nullptr, nullptr, MM, DD, HH, 1.f, nullptr, ao);
}

// round 10
// speedup vs baseline: 12.5725x; 1.8127x over previous
#include <cuda_runtime.h>
#include <cuda_fp16.h>
#include <cstdint>
#include <cstddef>

// Problem constants
#define BB 8
#define NN 2048
#define DD 1024
#define CC 1024
#define HH 4096
#define HH2 (2*HH)
#define MM (BB*NN)          // 16384
#define EPSF 1e-6f

typedef __half fp16;

// ===========================================================================
// Helpers
// ===========================================================================
__device__ __forceinline__ uint32_t smem_u32(const void* p) {
    uint32_t a;
    asm("{ .reg .u64 t; cvta.to.shared.u64 t, %1; cvt.u32.u64 %0, t; }" : "=r"(a) : "l"(p));
    return a;
}
__device__ __forceinline__ void ldsm4(uint32_t* r, uint32_t addr) {
    asm volatile("ldmatrix.sync.aligned.m8n8.x4.shared.b16 {%0,%1,%2,%3}, [%4];"
        : "=r"(r[0]), "=r"(r[1]), "=r"(r[2]), "=r"(r[3]) : "r"(addr));
}
__device__ __forceinline__ void mma16816(float* d, const uint32_t* a, const uint32_t* b) {
    asm volatile("mma.sync.aligned.m16n8k16.row.col.f32.f16.f16.f32 "
        "{%0,%1,%2,%3}, {%4,%5,%6,%7}, {%8,%9}, {%0,%1,%2,%3};"
        : "+f"(d[0]), "+f"(d[1]), "+f"(d[2]), "+f"(d[3])
        : "r"(a[0]), "r"(a[1]), "r"(a[2]), "r"(a[3]), "r"(b[0]), "r"(b[1]));
}
__device__ __forceinline__ void cp_async16(uint32_t dst, const void* src) {
    asm volatile("cp.async.cg.shared.global [%0], [%1], 16;"
        :: "r"(dst), "l"(__cvta_generic_to_global(src)));
}
#define CP_COMMIT()  asm volatile("cp.async.commit_group;" ::: "memory")
#define CP_WAIT(n)   asm volatile("cp.async.wait_group %0;" :: "n"(n) : "memory")

__device__ __forceinline__ void split_h(float x, fp16& h, fp16& l) {
    h = __float2half_rn(x);
    l = __float2half_rn(x - __half2float(h));
}
__device__ __forceinline__ uint32_t pack_h2(fp16 a, fp16 b) {
    __half2 p; p.x = a; p.y = b;
    return *(uint32_t*)&p;
}

// ===========================================================================
// Scratch (device globals)
// ===========================================================================
__device__ __align__(16) fp16 g_wqT[DD*DD];
__device__ __align__(16) fp16 g_wkT[DD*DD];
__device__ __align__(16) fp16 g_wvT[DD*DD];
__device__ __align__(16) fp16 g_wcT[DD*DD];
__device__ __align__(16) fp16 g_w13T[(size_t)HH2*DD];   // interleaved w1/w3 rows
__device__ __align__(16) fp16 g_w2T[(size_t)DD*HH];
__device__ __align__(16) fp16 g_nctx_h[CC*DD], g_nctx_l[CC*DD];
__device__ float g_kf[CC*DD];
__device__ float g_vf[CC*DD];
__device__ __align__(16) fp16 g_k[CC*DD];
__device__ __align__(16) fp16 g_vT[DD*CC];
__device__ __align__(16) fp16 g_nq_h[(size_t)MM*DD], g_nq_l[(size_t)MM*DD];
__device__ float g_qf[(size_t)MM*DD];
__device__ __align__(16) fp16 g_q_h[(size_t)MM*DD], g_q_l[(size_t)MM*DD];
__device__ __align__(16) fp16 g_z1[(size_t)MM*CC];
__device__ __align__(16) fp16 g_attn1[(size_t)MM*DD];
__device__ float g_yf[(size_t)MM*DD];
__device__ float g_ao[(size_t)MM*DD];
__device__ __align__(16) fp16 g_h1[(size_t)MM*DD];
__device__ __align__(16) fp16 g_p1[(size_t)MM*HH];
__device__ float g_invf[512];

// ===========================================================================
// fp16 GEMM via mma.sync: C[M,N] = alpha*A@B^T (+bias)(+addm)
//   SPLIT=true : A = Ah+Al (2 MMAs, ~22-bit A)     — for the log_alpha path
//   SPLIT=false: A = Ah single fp16 (1 MMA)        — FFN / attn chain
// outmode: 0 = fp32 C (+bias/+addm), 1 = fp16 out, 2 = silu-pair fp16 out
//   (mode 2: N covers interleaved w1|w3 pairs; out[row, col/2] = silu(x0)*x1)
// 256 threads, CTA 128x128, BK=32, 2-stage cp.async, pitch-40 smem.
// ===========================================================================
#define TILE_BYTES (128 * 40 * 2)   // 10240

template <bool SPLIT>
__device__ __forceinline__ void stage_load(
    uint32_t sm_stage, const fp16* __restrict__ Ah, const fp16* __restrict__ Al,
    const fp16* __restrict__ B, int bm, int bn, int K, int k0, int tid)
{
    constexpr int NT = SPLIT ? 3 : 2;
    #pragma unroll
    for (int t = 0; t < NT; t++) {
        const fp16* gb;
        int brow;
        if (SPLIT) { gb = (t == 0) ? Ah : (t == 1) ? Al : B; brow = (t < 2) ? bm : bn; }
        else       { gb = (t == 0) ? Ah : B;                 brow = (t < 1) ? bm : bn; }
        gb += (size_t)brow * K + k0;
        const uint32_t sb = sm_stage + t * TILE_BYTES;
        #pragma unroll
        for (int j = 0; j < 2; j++) {
            const int c = tid + j * 256;
            const int row = c >> 2, ch = c & 3;
            cp_async16(sb + row * 80 + ch * 16, gb + (size_t)row * K + ch * 8);
        }
    }
}

template <bool SPLIT>
__global__ __launch_bounds__(256, 2)
void fp16_gemm(const fp16* __restrict__ Ah, const fp16* __restrict__ Al,
               const fp16* __restrict__ B,
               float* __restrict__ Cf, fp16* __restrict__ OutH, int outmode,
               int M, int N, int K, float alpha,
               const float* __restrict__ bias, const float* __restrict__ addm)
{
    constexpr int NSPLIT = SPLIT ? 2 : 1;
    constexpr uint32_t STB = (NSPLIT + 1) * TILE_BYTES;

    extern __shared__ char smem[];
    const uint32_t sb = smem_u32(smem);
    const int tid = threadIdx.x, wid = tid >> 5, lane = tid & 31;
    const int bm = blockIdx.y * 128, bn = blockIdx.x * 128;
    const int wm = (wid >> 1) * 32, wn = (wid & 1) * 64;

    float acc[2][8][4];
    #pragma unroll
    for (int i = 0; i < 2; i++)
        #pragma unroll
        for (int j = 0; j < 8; j++)
            #pragma unroll
            for (int q = 0; q < 4; q++) acc[i][j][q] = 0.f;

    const uint32_t aoff = (uint32_t)((wm + (lane & 15)) * 80 + (lane >> 4) * 16);
    const uint32_t boff = (uint32_t)((wn + (lane & 7) + ((lane >> 4) & 1) * 8) * 80
                                     + ((lane >> 3) & 1) * 16);

    const int S = K >> 5;
    stage_load<SPLIT>(sb, Ah, Al, B, bm, bn, K, 0, tid);
    CP_COMMIT();

    for (int s = 0; s < S; s++) {
        if (s + 1 < S) {
            stage_load<SPLIT>(sb + ((s + 1) & 1) * STB, Ah, Al, B, bm, bn, K, (s + 1) << 5, tid);
            CP_COMMIT();
            CP_WAIT(1);
        } else {
            CP_WAIT(0);
        }
        __syncthreads();

        const uint32_t stg = sb + (s & 1) * STB;
        const uint32_t tB = stg + NSPLIT * TILE_BYTES;

        #pragma unroll
        for (int ks = 0; ks < 2; ks++) {
            const uint32_t ko = ks * 32;
            uint32_t a[NSPLIT][2][4];
            uint32_t b[4][4];
            #pragma unroll
            for (int sp = 0; sp < NSPLIT; sp++)
                #pragma unroll
                for (int mt = 0; mt < 2; mt++)
                    ldsm4(a[sp][mt], stg + sp * TILE_BYTES + aoff + mt * (16 * 80) + ko);
            #pragma unroll
            for (int bt = 0; bt < 4; bt++)
                ldsm4(b[bt], tB + boff + bt * (16 * 80) + ko);
            #pragma unroll
            for (int mt = 0; mt < 2; mt++)
                #pragma unroll
                for (int bt = 0; bt < 4; bt++)
                    #pragma unroll
                    for (int hf = 0; hf < 2; hf++) {
                        const int nt = bt * 2 + hf;
                        #pragma unroll
                        for (int sp = 0; sp < NSPLIT; sp++)
                            mma16816(acc[mt][nt], a[sp][mt], &b[bt][hf * 2]);
                    }
        }
        __syncthreads();
    }

    // ---- epilogue ----
    const int g = lane >> 2, qd = lane & 3;
    #pragma unroll
    for (int mt = 0; mt < 2; mt++) {
        const int r0 = bm + wm + mt * 16 + g;
        #pragma unroll
        for (int nt = 0; nt < 8; nt++) {
            const int col = bn + wn + nt * 8 + qd * 2;
            #pragma unroll
            for (int half = 0; half < 2; half++) {
                const int row = r0 + half * 8;
                float x0 = acc[mt][nt][half * 2 + 0] * alpha;
                float x1 = acc[mt][nt][half * 2 + 1] * alpha;
                if (outmode == 0) {
                    const size_t idx = (size_t)row * N + col;
                    if (bias) { x0 += bias[col]; x1 += bias[col + 1]; }
                    if (addm) {
                        const float2 a2 = *(const float2*)&addm[idx];
                        x0 += a2.x; x1 += a2.y;
                    }
                    *(float2*)&Cf[idx] = make_float2(x0, x1);
                } else if (outmode == 1) {
                    const size_t idx = (size_t)row * N + col;
                    *(uint32_t*)(OutH + idx) = pack_h2(__float2half_rn(x0), __float2half_rn(x1));
                } else {
                    // silu-pair: (x0, x1) = (w1 val, w3 val) for output col/2
                    const float pv = (x0 / (1.0f + __expf(-x0))) * x1;
                    OutH[(size_t)row * (N >> 1) + (col >> 1)] = __float2half_rn(pv);
                }
            }
        }
    }
}

// ===========================================================================
// Transpose + convert: src fp32 [R,C] -> dst fp16, dst row = rowmul*c + rowoff
// ===========================================================================
__global__ __launch_bounds__(256)
void transconv_kernel(const float* __restrict__ src, int R, int C,
                      fp16* __restrict__ dst, int rowmul, int rowoff)
{
    __shared__ float t[32][33];
    const int c0 = blockIdx.x * 32, r0 = blockIdx.y * 32;
    const int tx = threadIdx.x & 31, ty = threadIdx.x >> 5;
    #pragma unroll
    for (int i = 0; i < 4; i++)
        t[ty + i * 8][tx] = src[(size_t)(r0 + ty + i * 8) * C + c0 + tx];
    __syncthreads();
    #pragma unroll
    for (int i = 0; i < 4; i++) {
        const float x = t[tx][ty + i * 8];
        const size_t drow = (size_t)(c0 + ty + i * 8) * rowmul + rowoff;
        dst[drow * R + r0 + tx] = __float2half_rn(x);
    }
}

// ===========================================================================
// Block reductions (256 threads)
// ===========================================================================
__device__ __forceinline__ float block_reduce_sum(float v) {
    __shared__ float red[8];
    const int lane = threadIdx.x & 31, wid = threadIdx.x >> 5;
    #pragma unroll
    for (int o = 16; o > 0; o >>= 1) v += __shfl_down_sync(0xffffffffu, v, o);
    __syncthreads();
    if (lane == 0) red[wid] = v;
    __syncthreads();
    float r = 0.f;
    if (threadIdx.x < 8) r = red[threadIdx.x];
    if (wid == 0) {
        #pragma unroll
        for (int o = 4; o > 0; o >>= 1) r += __shfl_down_sync(0xffu, r, o);
        if (lane == 0) red[0] = r;
    }
    __syncthreads();
    return red[0];
}
__device__ __forceinline__ float block_reduce_max(float v) {
    __shared__ float red[8];
    const int lane = threadIdx.x & 31, wid = threadIdx.x >> 5;
    #pragma unroll
    for (int o = 16; o > 0; o >>= 1) v = fmaxf(v, __shfl_down_sync(0xffffffffu, v, o));
    __syncthreads();
    if (lane == 0) red[wid] = v;
    __syncthreads();
    float r = -3.0e38f;
    if (threadIdx.x < 8) r = red[threadIdx.x];
    if (wid == 0) {
        #pragma unroll
        for (int o = 4; o > 0; o >>= 1) r = fmaxf(r, __shfl_down_sync(0xffu, r, o));
        if (lane == 0) red[0] = r;
    }
    __syncthreads();
    return red[0];
}

// ===========================================================================
// inv_freq table
// ===========================================================================
__global__ void init_invf_kernel(float* __restrict__ invf)
{
    const int j = threadIdx.x;                // 512 threads
    const float L2B = 13.28771237954945f;     // log2(10000)
    invf[j] = exp2f(-(float)j * (L2B / 512.0f));
}

// ===========================================================================
// RMSNorm -> split fp16 (ol != null) or single fp16 (ol == null).
// ===========================================================================
__global__ __launch_bounds__(256)
void rmsnorm_h_kernel(const float* __restrict__ x, const float* __restrict__ g,
                      fp16* __restrict__ oh, fp16* __restrict__ ol)
{
    const size_t row = blockIdx.x;
    const int i = threadIdx.x * 4;
    const float4 v = *(const float4*)&x[row * DD + i];
    float ss = v.x*v.x + v.y*v.y + v.z*v.z + v.w*v.w;
    ss = block_reduce_sum(ss);
    const float inv = rsqrtf(ss * (1.0f / DD) + EPSF);
    const float4 gg = *(const float4*)&g[i];
    const float o0 = v.x*inv*gg.x, o1 = v.y*inv*gg.y, o2 = v.z*inv*gg.z, o3 = v.w*inv*gg.w;
    const size_t idx = row * DD + i;
    if (ol) {
        fp16 h0,l0,h1,l1,h2,l2,h3,l3;
        split_h(o0,h0,l0); split_h(o1,h1,l1); split_h(o2,h2,l2); split_h(o3,h3,l3);
        *(uint2*)(oh + idx) = make_uint2(pack_h2(h0,h1), pack_h2(h2,h3));
        *(uint2*)(ol + idx) = make_uint2(pack_h2(l0,l1), pack_h2(l2,l3));
    } else {
        *(uint2*)(oh + idx) = make_uint2(
            pack_h2(__float2half_rn(o0), __float2half_rn(o1)),
            pack_h2(__float2half_rn(o2), __float2half_rn(o3)));
    }
}

// ===========================================================================
// RoPE: read fp32, write split fp16 (ol != null) or single (ol == null).
// ===========================================================================
__global__ __launch_bounds__(256)
void rope_h_kernel(const float* __restrict__ x, const int* __restrict__ positions,
                   const float* __restrict__ invf,
                   fp16* __restrict__ oh, fp16* __restrict__ ol)
{
    const size_t row = blockIdx.x;
    const float p = (float)positions[row];
    const float* xr = x + row * DD;
    #pragma unroll
    for (int jj = 0; jj < 2; jj++) {
        const int j = threadIdx.x + jj * 256;
        float s, c;
        sincosf(p * __ldg(&invf[j]), &s, &c);
        const float x1 = xr[2*j], x2 = xr[2*j + 1];
        const float r1 = x1 * c - x2 * s;
        const float r2 = x1 * s + x2 * c;
        const size_t idx = row * DD + 2*j;
        if (ol) {
            fp16 h1, l1, h2, l2;
            split_h(r1, h1, l1); split_h(r2, h2, l2);
            *(uint32_t*)(oh + idx) = pack_h2(h1, h2);
            *(uint32_t*)(ol + idx) = pack_h2(l1, l2);
        } else {
            *(uint32_t*)(oh + idx) = pack_h2(__float2half_rn(r1), __float2half_rn(r2));
        }
    }
}

// ===========================================================================
// Gumbel + softmax over C=1024; writes log_alpha_tau, z (fp32), z fp16.
// Precise logf (fast __logf corrupts the u->1 tail); fast __expf is safe.
// ===========================================================================
__global__ __launch_bounds__(256)
void gumbel_softmax_kernel(const float* __restrict__ la, const float* __restrict__ noise,
                           const float* __restrict__ tau_p, const float* __restrict__ gns_p,
                           float* __restrict__ lat_out, float* __restrict__ z_out,
                           fp16* __restrict__ zh)
{
    const size_t row = blockIdx.x;
    const float inv_tau = 1.0f / (*tau_p);
    const float gns = *gns_p;
    const size_t base = row * CC + threadIdx.x * 4;

    const float4 la4 = *(const float4*)&la[base];
    const float4 u4  = *(const float4*)&noise[base];
    float lt[4];
    const float u[4] = {u4.x, u4.y, u4.z, u4.w};
    const float l[4] = {la4.x, la4.y, la4.z, la4.w};
    #pragma unroll
    for (int t = 0; t < 4; t++) {
        const float gum = -logf(-logf(u[t] + 1e-10f) + 1e-10f);
        lt[t] = (l[t] + gns * gum) * inv_tau;
    }
    *(float4*)&lat_out[base] = make_float4(lt[0], lt[1], lt[2], lt[3]);

    float m = fmaxf(fmaxf(lt[0], lt[1]), fmaxf(lt[2], lt[3]));
    m = block_reduce_max(m);
    float e[4], s = 0.f;
    #pragma unroll
    for (int t = 0; t < 4; t++) { e[t] = __expf(lt[t] - m); s += e[t]; }
    s = block_reduce_sum(s);
    const float invs = 1.0f / s;
    float z[4];
    #pragma unroll
    for (int t = 0; t < 4; t++) z[t] = e[t] * invs;
    *(float4*)&z_out[base] = make_float4(z[0], z[1], z[2], z[3]);
    *(uint2*)(zh + base) = make_uint2(
        pack_h2(__float2half_rn(z[0]), __float2half_rn(z[1])),
        pack_h2(__float2half_rn(z[2]), __float2half_rn(z[3])));
}

// ===========================================================================
// attn_out = rs*latents + y ; h = rmsnorm(attn_out)*g_ff -> single fp16.
// ===========================================================================
__global__ __launch_bounds__(256)
void residual_rms_kernel(const float* __restrict__ latents, const float* __restrict__ y,
                         const float* __restrict__ rs_p, const float* __restrict__ gff,
                         float* __restrict__ ao_out, fp16* __restrict__ hh)
{
    const size_t row = blockIdx.x;
    const float rs = *rs_p;
    const size_t base = row * DD + threadIdx.x * 4;
    const float4 l4 = *(const float4*)&latents[base];
    const float4 y4 = *(const float4*)&y[base];
    float4 ao;
    ao.x = rs*l4.x + y4.x; ao.y = rs*l4.y + y4.y;
    ao.z = rs*l4.z + y4.z; ao.w = rs*l4.w + y4.w;
    *(float4*)&ao_out[base] = ao;
    float ss = ao.x*ao.x + ao.y*ao.y + ao.z*ao.z + ao.w*ao.w;
    ss = block_reduce_sum(ss);
    const float inv = rsqrtf(ss * (1.0f / DD) + EPSF);
    const float4 g4 = *(const float4*)&gff[threadIdx.x * 4];
    *(uint2*)(hh + base) = make_uint2(
        pack_h2(__float2half_rn(ao.x*inv*g4.x), __float2half_rn(ao.y*inv*g4.y)),
        pack_h2(__float2half_rn(ao.z*inv*g4.z), __float2half_rn(ao.w*inv*g4.w)));
}

// ===========================================================================
// Launch
// ===========================================================================
extern "C" void kernel_launch(void* const* d_in, const int* in_sizes, int n_in,
                              void* d_out, int out_size)
{
    (void)in_sizes; (void)n_in; (void)out_size;

    const float* latents  = (const float*)d_in[0];
    const float* codebook = (const float*)d_in[1];
    const float* Wq       = (const float*)d_in[2];
    const float* Wk       = (const float*)d_in[3];
    const float* Wv       = (const float*)d_in[4];
    const float* bv       = (const float*)d_in[5];
    const float* Wc       = (const float*)d_in[6];
    const float* w1       = (const float*)d_in[7];
    const float* w2       = (const float*)d_in[8];
    const float* w3       = (const float*)d_in[9];
    const float* gctx     = (const float*)d_in[10];
    const float* gq       = (const float*)d_in[11];
    const float* gff      = (const float*)d_in[12];
    const float* noise    = (const float*)d_in[13];
    const int*   positions= (const int*)d_in[14];
    const float* tau      = (const float*)d_in[15];
    const float* rs       = (const float*)d_in[16];
    const float* gns      = (const float*)d_in[17];

    const int SMEM_SPLIT  = 2 * 3 * TILE_BYTES;   // 61440
    const int SMEM_SINGLE = 2 * 2 * TILE_BYTES;   // 40960
    cudaFuncSetAttribute(fp16_gemm<true>,  cudaFuncAttributeMaxDynamicSharedMemorySize, SMEM_SPLIT);
    cudaFuncSetAttribute(fp16_gemm<false>, cudaFuncAttributeMaxDynamicSharedMemorySize, SMEM_SINGLE);

    #define SYM(v, s) do { void* _p; cudaGetSymbolAddress(&_p, s); v = (decltype(v))_p; } while (0)
    fp16 *wqT,*wkT,*wvT,*wcT,*w13T,*w2T;
    fp16 *nctx_h,*nctx_l,*k1,*vT,*nq_h,*nq_l,*q_h,*q_l,*z1,*attn1,*h1,*p1;
    float *kf,*vf,*qf,*yf,*ao,*invf;
    SYM(wqT,g_wqT); SYM(wkT,g_wkT); SYM(wvT,g_wvT); SYM(wcT,g_wcT);
    SYM(w13T,g_w13T); SYM(w2T,g_w2T);
    SYM(nctx_h,g_nctx_h); SYM(nctx_l,g_nctx_l);
    SYM(k1,g_k); SYM(vT,g_vT);
    SYM(nq_h,g_nq_h); SYM(nq_l,g_nq_l); SYM(q_h,g_q_h); SYM(q_l,g_q_l);
    SYM(z1,g_z1); SYM(attn1,g_attn1); SYM(h1,g_h1); SYM(p1,g_p1);
    SYM(kf,g_kf); SYM(vf,g_vf); SYM(qf,g_qf); SYM(yf,g_yf); SYM(ao,g_ao);
    SYM(invf,g_invf);
    #undef SYM

    float* out_cb  = (float*)d_out;
    float* out_la  = out_cb  + (size_t)MM * DD;
    float* out_lat = out_la  + (size_t)MM * CC;
    float* out_z   = out_lat + (size_t)MM * CC;

    const float inv_scale = 1.0f / 32.0f;   // 1/sqrt(1024)

    init_invf_kernel<<<1, 512>>>(invf);
    rmsnorm_h_kernel<<<CC, 256>>>(codebook, gctx, nctx_h, nctx_l);
    rmsnorm_h_kernel<<<MM, 256>>>(latents, gq, nq_h, nq_l);
    transconv_kernel<<<dim3(DD/32, DD/32), 256>>>(Wq, DD, DD, wqT, 1, 0);
    transconv_kernel<<<dim3(DD/32, DD/32), 256>>>(Wk, DD, DD, wkT, 1, 0);
    fp16_gemm<true><<<dim3(DD/128, MM/128), 256, SMEM_SPLIT>>>(
        nq_h, nq_l, wqT, qf, nullptr, 0, MM, DD, DD, 1.f, nullptr, nullptr);

    transconv_kernel<<<dim3(DD/32, DD/32), 256>>>(Wv, DD, DD, wvT, 1, 0);
    transconv_kernel<<<dim3(DD/32, DD/32), 256>>>(Wc, DD, DD, wcT, 1, 0);
    transconv_kernel<<<dim3(HH/32, DD/32), 256>>>(w1, DD, HH, w13T, 2, 0);  // even rows
    transconv_kernel<<<dim3(HH/32, DD/32), 256>>>(w3, DD, HH, w13T, 2, 1);  // odd rows
    transconv_kernel<<<dim3(DD/32, HH/32), 256>>>(w2, HH, DD, w2T, 1, 0);

    // --- context path (split A, tiny) ---
    fp16_gemm<true><<<dim3(DD/128, CC/128), 256, SMEM_SPLIT>>>(
        nctx_h, nctx_l, wkT, kf, nullptr, 0, CC, DD, DD, 1.f, nullptr, nullptr);
    fp16_gemm<true><<<dim3(DD/128, CC/128), 256, SMEM_SPLIT>>>(
        nctx_h, nctx_l, wvT, vf, nullptr, 0, CC, DD, DD, 1.f, bv, nullptr);
    rope_h_kernel<<<CC, 256>>>(kf, positions, invf, k1, nullptr);
    transconv_kernel<<<dim3(DD/32, CC/32), 256>>>(vf, CC, DD, vT, 1, 0);

    // --- query path (split A) ---
    rope_h_kernel<<<MM, 256>>>(qf, positions, invf, q_h, q_l);
    fp16_gemm<true><<<dim3(CC/128, MM/128), 256, SMEM_SPLIT>>>(
        q_h, q_l, k1, out_la, nullptr, 0, MM, CC, DD, inv_scale, nullptr, nullptr);

    // gumbel + softmax
    gumbel_softmax_kernel<<<MM, 256>>>(out_la, noise, tau, gns, out_lat, out_z, z1);

    // --- attn / FFN chain (single A) ---
    fp16_gemm<false><<<dim3(DD/128, MM/128), 256, SMEM_SINGLE>>>(
        z1, nullptr, vT, nullptr, attn1, 1, MM, DD, CC, 1.f, nullptr, nullptr);
    fp16_gemm<false><<<dim3(DD/128, MM/128), 256, SMEM_SINGLE>>>(
        attn1, nullptr, wcT, yf, nullptr, 0, MM, DD, DD, 1.f, nullptr, nullptr);
    residual_rms_kernel<<<MM, 256>>>(latents, yf, rs, gff, ao, h1);
    fp16_gemm<false><<<dim3(HH2/128, MM/128), 256, SMEM_SINGLE>>>(
        h1, nullptr, w13T, nullptr, p1, 2, MM, HH2, DD, 1.f, nullptr, nullptr);
    fp16_gemm<false><<<dim3(DD/128, MM/128), 256, SMEM_SINGLE>>>(
        p1, nullptr, w2T, out_cb, nullptr, 0, MM, DD, HH, 1.f, nullptr, ao);
}

// round 11
// speedup vs baseline: 13.8342x; 1.1004x over previous
#include <cuda_runtime.h>
#include <cuda_fp16.h>
#include <cstdint>
#include <cstddef>

// Problem constants
#define BB 8
#define NN 2048
#define DD 1024
#define CC 1024
#define HH 4096
#define HH2 (2*HH)
#define MM (BB*NN)          // 16384
#define EPSF 1e-6f

typedef __half fp16;

// ===========================================================================
// Helpers
// ===========================================================================
__device__ __forceinline__ uint32_t smem_u32(const void* p) {
    uint32_t a;
    asm("{ .reg .u64 t; cvta.to.shared.u64 t, %1; cvt.u32.u64 %0, t; }" : "=r"(a) : "l"(p));
    return a;
}
__device__ __forceinline__ void ldsm4(uint32_t* r, uint32_t addr) {
    asm volatile("ldmatrix.sync.aligned.m8n8.x4.shared.b16 {%0,%1,%2,%3}, [%4];"
        : "=r"(r[0]), "=r"(r[1]), "=r"(r[2]), "=r"(r[3]) : "r"(addr));
}
__device__ __forceinline__ void mma16816(float* d, const uint32_t* a, const uint32_t* b) {
    asm volatile("mma.sync.aligned.m16n8k16.row.col.f32.f16.f16.f32 "
        "{%0,%1,%2,%3}, {%4,%5,%6,%7}, {%8,%9}, {%0,%1,%2,%3};"
        : "+f"(d[0]), "+f"(d[1]), "+f"(d[2]), "+f"(d[3])
        : "r"(a[0]), "r"(a[1]), "r"(a[2]), "r"(a[3]), "r"(b[0]), "r"(b[1]));
}
__device__ __forceinline__ void cp_async16(uint32_t dst, const void* src) {
    asm volatile("cp.async.cg.shared.global [%0], [%1], 16;"
        :: "r"(dst), "l"(__cvta_generic_to_global(src)));
}
#define CP_COMMIT()  asm volatile("cp.async.commit_group;" ::: "memory")
#define CP_WAIT(n)   asm volatile("cp.async.wait_group %0;" :: "n"(n) : "memory")

__device__ __forceinline__ void split_h(float x, fp16& h, fp16& l) {
    h = __float2half_rn(x);
    l = __float2half_rn(x - __half2float(h));
}
__device__ __forceinline__ uint32_t pack_h2(fp16 a, fp16 b) {
    __half2 p; p.x = a; p.y = b;
    return *(uint32_t*)&p;
}

// ===========================================================================
// Scratch (device globals)
// ===========================================================================
__device__ __align__(16) fp16 g_wqT[DD*DD];
__device__ __align__(16) fp16 g_wkT[DD*DD];
__device__ __align__(16) fp16 g_wvT[DD*DD];
__device__ __align__(16) fp16 g_wcT[DD*DD];
__device__ __align__(16) fp16 g_w13T[(size_t)HH2*DD];   // interleaved w1/w3 rows
__device__ __align__(16) fp16 g_w2T[(size_t)DD*HH];
__device__ __align__(16) fp16 g_nctx_h[CC*DD], g_nctx_l[CC*DD];
__device__ float g_vf[CC*DD];
__device__ __align__(16) fp16 g_k[CC*DD];
__device__ __align__(16) fp16 g_vT[DD*CC];
__device__ __align__(16) fp16 g_nq_h[(size_t)MM*DD], g_nq_l[(size_t)MM*DD];
__device__ __align__(16) fp16 g_q_h[(size_t)MM*DD], g_q_l[(size_t)MM*DD];
__device__ __align__(16) fp16 g_z1[(size_t)MM*CC];
__device__ __align__(16) fp16 g_attn1[(size_t)MM*DD];
__device__ float g_yf[(size_t)MM*DD];
__device__ float g_ao[(size_t)MM*DD];
__device__ __align__(16) fp16 g_h1[(size_t)MM*DD];
__device__ __align__(16) fp16 g_p1[(size_t)MM*HH];
__device__ float g_invf[512];

// ===========================================================================
// fp16 GEMM via mma.sync: C[M,N] = alpha*A@B^T (+bias)(+addm)
//   SPLIT=true : A = Ah+Al (2 MMAs, ~22-bit A)
//   SPLIT=false: A = Ah single fp16 (1 MMA)
// outmode: 0 = fp32 C (+bias/+addm), 1 = fp16 out, 2 = silu-pair fp16 out,
//          3 = rope + split fp16 out (OutH,OutL), 4 = rope + single fp16 out
// 256 threads, CTA 128x128, BK=64, 2-stage cp.async, pitch-72 smem (144 B).
// ===========================================================================
#define TILE_BYTES (128 * 72 * 2)   // 18432

template <bool SPLIT>
__device__ __forceinline__ void stage_load(
    uint32_t sm_stage, const fp16* __restrict__ Ah, const fp16* __restrict__ Al,
    const fp16* __restrict__ B, int bm, int bn, int K, int k0, int tid)
{
    constexpr int NT = SPLIT ? 3 : 2;
    #pragma unroll
    for (int t = 0; t < NT; t++) {
        const fp16* gb;
        int brow;
        if (SPLIT) { gb = (t == 0) ? Ah : (t == 1) ? Al : B; brow = (t < 2) ? bm : bn; }
        else       { gb = (t == 0) ? Ah : B;                 brow = (t < 1) ? bm : bn; }
        gb += (size_t)brow * K + k0;
        const uint32_t sb = sm_stage + t * TILE_BYTES;
        #pragma unroll
        for (int j = 0; j < 4; j++) {
            const int c = tid + j * 256;         // 0..1023
            const int row = c >> 3, ch = c & 7;  // 64 fp16 = 8 x 16B chunks
            cp_async16(sb + row * 144 + ch * 16, gb + (size_t)row * K + ch * 8);
        }
    }
}

template <bool SPLIT>
__global__ __launch_bounds__(256, 2)
void fp16_gemm(const fp16* __restrict__ Ah, const fp16* __restrict__ Al,
               const fp16* __restrict__ B,
               float* __restrict__ Cf, fp16* __restrict__ OutH, fp16* __restrict__ OutL,
               int outmode, int M, int N, int K, float alpha,
               const float* __restrict__ bias, const float* __restrict__ addm,
               const int* __restrict__ positions, const float* __restrict__ invf)
{
    constexpr int NSPLIT = SPLIT ? 2 : 1;
    constexpr uint32_t STB = (NSPLIT + 1) * TILE_BYTES;

    extern __shared__ char smem[];
    const uint32_t sb = smem_u32(smem);
    const int tid = threadIdx.x, wid = tid >> 5, lane = tid & 31;
    const int bm = blockIdx.y * 128, bn = blockIdx.x * 128;
    const int wm = (wid >> 1) * 32, wn = (wid & 1) * 64;

    float acc[2][8][4];
    #pragma unroll
    for (int i = 0; i < 2; i++)
        #pragma unroll
        for (int j = 0; j < 8; j++)
            #pragma unroll
            for (int q = 0; q < 4; q++) acc[i][j][q] = 0.f;

    const uint32_t aoff = (uint32_t)((wm + (lane & 15)) * 144 + (lane >> 4) * 16);
    const uint32_t boff = (uint32_t)((wn + (lane & 7) + ((lane >> 4) & 1) * 8) * 144
                                     + ((lane >> 3) & 1) * 16);

    const int S = K >> 6;   // K/64 stages
    stage_load<SPLIT>(sb, Ah, Al, B, bm, bn, K, 0, tid);
    CP_COMMIT();

    for (int s = 0; s < S; s++) {
        if (s + 1 < S) {
            stage_load<SPLIT>(sb + ((s + 1) & 1) * STB, Ah, Al, B, bm, bn, K, (s + 1) << 6, tid);
            CP_COMMIT();
            CP_WAIT(1);
        } else {
            CP_WAIT(0);
        }
        __syncthreads();

        const uint32_t stg = sb + (s & 1) * STB;
        const uint32_t tB = stg + NSPLIT * TILE_BYTES;

        #pragma unroll
        for (int ks = 0; ks < 4; ks++) {
            const uint32_t ko = ks * 32;
            uint32_t a[NSPLIT][2][4];
            uint32_t b[4][4];
            #pragma unroll
            for (int sp = 0; sp < NSPLIT; sp++)
                #pragma unroll
                for (int mt = 0; mt < 2; mt++)
                    ldsm4(a[sp][mt], stg + sp * TILE_BYTES + aoff + mt * (16 * 144) + ko);
            #pragma unroll
            for (int bt = 0; bt < 4; bt++)
                ldsm4(b[bt], tB + boff + bt * (16 * 144) + ko);
            #pragma unroll
            for (int mt = 0; mt < 2; mt++)
                #pragma unroll
                for (int bt = 0; bt < 4; bt++)
                    #pragma unroll
                    for (int hf = 0; hf < 2; hf++) {
                        const int nt = bt * 2 + hf;
                        #pragma unroll
                        for (int sp = 0; sp < NSPLIT; sp++)
                            mma16816(acc[mt][nt], a[sp][mt], &b[bt][hf * 2]);
                    }
        }
        __syncthreads();
    }

    // ---- epilogue ----
    const int g = lane >> 2, qd = lane & 3;
    #pragma unroll
    for (int mt = 0; mt < 2; mt++) {
        const int r0 = bm + wm + mt * 16 + g;
        #pragma unroll
        for (int nt = 0; nt < 8; nt++) {
            const int col = bn + wn + nt * 8 + qd * 2;
            #pragma unroll
            for (int half = 0; half < 2; half++) {
                const int row = r0 + half * 8;
                float x0 = acc[mt][nt][half * 2 + 0] * alpha;
                float x1 = acc[mt][nt][half * 2 + 1] * alpha;
                if (outmode == 0) {
                    const size_t idx = (size_t)row * N + col;
                    if (bias) { x0 += bias[col]; x1 += bias[col + 1]; }
                    if (addm) {
                        const float2 a2 = *(const float2*)&addm[idx];
                        x0 += a2.x; x1 += a2.y;
                    }
                    *(float2*)&Cf[idx] = make_float2(x0, x1);
                } else if (outmode == 1) {
                    const size_t idx = (size_t)row * N + col;
                    *(uint32_t*)(OutH + idx) = pack_h2(__float2half_rn(x0), __float2half_rn(x1));
                } else if (outmode == 2) {
                    // silu-pair: (x0, x1) = (w1 val, w3 val) for output col/2
                    const float pv = (x0 / (1.0f + __expf(-x0))) * x1;
                    OutH[(size_t)row * (N >> 1) + (col >> 1)] = __float2half_rn(pv);
                } else {
                    // rope: (x0, x1) = interleaved pair, j = col/2
                    const float p = (float)__ldg(&positions[row]);
                    float sn, cs;
                    sincosf(p * __ldg(&invf[col >> 1]), &sn, &cs);
                    const float r1 = x0 * cs - x1 * sn;
                    const float r2 = x0 * sn + x1 * cs;
                    const size_t idx = (size_t)row * N + col;
                    if (outmode == 3) {
                        fp16 h1, l1, h2, l2;
                        split_h(r1, h1, l1); split_h(r2, h2, l2);
                        *(uint32_t*)(OutH + idx) = pack_h2(h1, h2);
                        *(uint32_t*)(OutL + idx) = pack_h2(l1, l2);
                    } else {
                        *(uint32_t*)(OutH + idx) = pack_h2(__float2half_rn(r1), __float2half_rn(r2));
                    }
                }
            }
        }
    }
}

// ===========================================================================
// Transpose + convert: src fp32 [R,C] -> dst fp16, dst row = rowmul*c + rowoff
// ===========================================================================
__global__ __launch_bounds__(256)
void transconv_kernel(const float* __restrict__ src, int R, int C,
                      fp16* __restrict__ dst, int rowmul, int rowoff)
{
    __shared__ float t[32][33];
    const int c0 = blockIdx.x * 32, r0 = blockIdx.y * 32;
    const int tx = threadIdx.x & 31, ty = threadIdx.x >> 5;
    #pragma unroll
    for (int i = 0; i < 4; i++)
        t[ty + i * 8][tx] = src[(size_t)(r0 + ty + i * 8) * C + c0 + tx];
    __syncthreads();
    #pragma unroll
    for (int i = 0; i < 4; i++) {
        const float x = t[tx][ty + i * 8];
        const size_t drow = (size_t)(c0 + ty + i * 8) * rowmul + rowoff;
        dst[drow * R + r0 + tx] = __float2half_rn(x);
    }
}

// ===========================================================================
// Block reductions (256 threads)
// ===========================================================================
__device__ __forceinline__ float block_reduce_sum(float v) {
    __shared__ float red[8];
    const int lane = threadIdx.x & 31, wid = threadIdx.x >> 5;
    #pragma unroll
    for (int o = 16; o > 0; o >>= 1) v += __shfl_down_sync(0xffffffffu, v, o);
    __syncthreads();
    if (lane == 0) red[wid] = v;
    __syncthreads();
    float r = 0.f;
    if (threadIdx.x < 8) r = red[threadIdx.x];
    if (wid == 0) {
        #pragma unroll
        for (int o = 4; o > 0; o >>= 1) r += __shfl_down_sync(0xffu, r, o);
        if (lane == 0) red[0] = r;
    }
    __syncthreads();
    return red[0];
}
__device__ __forceinline__ float block_reduce_max(float v) {
    __shared__ float red[8];
    const int lane = threadIdx.x & 31, wid = threadIdx.x >> 5;
    #pragma unroll
    for (int o = 16; o > 0; o >>= 1) v = fmaxf(v, __shfl_down_sync(0xffffffffu, v, o));
    __syncthreads();
    if (lane == 0) red[wid] = v;
    __syncthreads();
    float r = -3.0e38f;
    if (threadIdx.x < 8) r = red[threadIdx.x];
    if (wid == 0) {
        #pragma unroll
        for (int o = 4; o > 0; o >>= 1) r = fmaxf(r, __shfl_down_sync(0xffu, r, o));
        if (lane == 0) red[0] = r;
    }
    __syncthreads();
    return red[0];
}

// ===========================================================================
// inv_freq table
// ===========================================================================
__global__ void init_invf_kernel(float* __restrict__ invf)
{
    const int j = threadIdx.x;                // 512 threads
    const float L2B = 13.28771237954945f;     // log2(10000)
    invf[j] = exp2f(-(float)j * (L2B / 512.0f));
}

// ===========================================================================
// RMSNorm -> split fp16. One block (256 thr) per row of 1024.
// ===========================================================================
__global__ __launch_bounds__(256)
void rmsnorm_h_kernel(const float* __restrict__ x, const float* __restrict__ g,
                      fp16* __restrict__ oh, fp16* __restrict__ ol)
{
    const size_t row = blockIdx.x;
    const int i = threadIdx.x * 4;
    const float4 v = *(const float4*)&x[row * DD + i];
    float ss = v.x*v.x + v.y*v.y + v.z*v.z + v.w*v.w;
    ss = block_reduce_sum(ss);
    const float inv = rsqrtf(ss * (1.0f / DD) + EPSF);
    const float4 gg = *(const float4*)&g[i];
    const float o0 = v.x*inv*gg.x, o1 = v.y*inv*gg.y, o2 = v.z*inv*gg.z, o3 = v.w*inv*gg.w;
    const size_t idx = row * DD + i;
    fp16 h0,l0,h1,l1,h2,l2,h3,l3;
    split_h(o0,h0,l0); split_h(o1,h1,l1); split_h(o2,h2,l2); split_h(o3,h3,l3);
    *(uint2*)(oh + idx) = make_uint2(pack_h2(h0,h1), pack_h2(h2,h3));
    *(uint2*)(ol + idx) = make_uint2(pack_h2(l0,l1), pack_h2(l2,l3));
}

// ===========================================================================
// Gumbel + softmax over C=1024; writes log_alpha_tau, z (fp32), z fp16.
// Precise logf (fast __logf corrupts the u->1 tail); fast __expf is safe.
// ===========================================================================
__global__ __launch_bounds__(256)
void gumbel_softmax_kernel(const float* __restrict__ la, const float* __restrict__ noise,
                           const float* __restrict__ tau_p, const float* __restrict__ gns_p,
                           float* __restrict__ lat_out, float* __restrict__ z_out,
                           fp16* __restrict__ zh)
{
    const size_t row = blockIdx.x;
    const float inv_tau = 1.0f / (*tau_p);
    const float gns = *gns_p;
    const size_t base = row * CC + threadIdx.x * 4;

    const float4 la4 = *(const float4*)&la[base];
    const float4 u4  = *(const float4*)&noise[base];
    float lt[4];
    const float u[4] = {u4.x, u4.y, u4.z, u4.w};
    const float l[4] = {la4.x, la4.y, la4.z, la4.w};
    #pragma unroll
    for (int t = 0; t < 4; t++) {
        const float gum = -logf(-logf(u[t] + 1e-10f) + 1e-10f);
        lt[t] = (l[t] + gns * gum) * inv_tau;
    }
    *(float4*)&lat_out[base] = make_float4(lt[0], lt[1], lt[2], lt[3]);

    float m = fmaxf(fmaxf(lt[0], lt[1]), fmaxf(lt[2], lt[3]));
    m = block_reduce_max(m);
    float e[4], s = 0.f;
    #pragma unroll
    for (int t = 0; t < 4; t++) { e[t] = __expf(lt[t] - m); s += e[t]; }
    s = block_reduce_sum(s);
    const float invs = 1.0f / s;
    float z[4];
    #pragma unroll
    for (int t = 0; t < 4; t++) z[t] = e[t] * invs;
    *(float4*)&z_out[base] = make_float4(z[0], z[1], z[2], z[3]);
    *(uint2*)(zh + base) = make_uint2(
        pack_h2(__float2half_rn(z[0]), __float2half_rn(z[1])),
        pack_h2(__float2half_rn(z[2]), __float2half_rn(z[3])));
}

// ===========================================================================
// attn_out = rs*latents + y ; h = rmsnorm(attn_out)*g_ff -> single fp16.
// ===========================================================================
__global__ __launch_bounds__(256)
void residual_rms_kernel(const float* __restrict__ latents, const float* __restrict__ y,
                         const float* __restrict__ rs_p, const float* __restrict__ gff,
                         float* __restrict__ ao_out, fp16* __restrict__ hh)
{
    const size_t row = blockIdx.x;
    const float rs = *rs_p;
    const size_t base = row * DD + threadIdx.x * 4;
    const float4 l4 = *(const float4*)&latents[base];
    const float4 y4 = *(const float4*)&y[base];
    float4 ao;
    ao.x = rs*l4.x + y4.x; ao.y = rs*l4.y + y4.y;
    ao.z = rs*l4.z + y4.z; ao.w = rs*l4.w + y4.w;
    *(float4*)&ao_out[base] = ao;
    float ss = ao.x*ao.x + ao.y*ao.y + ao.z*ao.z + ao.w*ao.w;
    ss = block_reduce_sum(ss);
    const float inv = rsqrtf(ss * (1.0f / DD) + EPSF);
    const float4 g4 = *(const float4*)&gff[threadIdx.x * 4];
    *(uint2*)(hh + base) = make_uint2(
        pack_h2(__float2half_rn(ao.x*inv*g4.x), __float2half_rn(ao.y*inv*g4.y)),
        pack_h2(__float2half_rn(ao.z*inv*g4.z), __float2half_rn(ao.w*inv*g4.w)));
}

// ===========================================================================
// Launch
// ===========================================================================
extern "C" void kernel_launch(void* const* d_in, const int* in_sizes, int n_in,
                              void* d_out, int out_size)
{
    (void)in_sizes; (void)n_in; (void)out_size;

    const float* latents  = (const float*)d_in[0];
    const float* codebook = (const float*)d_in[1];
    const float* Wq       = (const float*)d_in[2];
    const float* Wk       = (const float*)d_in[3];
    const float* Wv       = (const float*)d_in[4];
    const float* bv       = (const float*)d_in[5];
    const float* Wc       = (const float*)d_in[6];
    const float* w1       = (const float*)d_in[7];
    const float* w2       = (const float*)d_in[8];
    const float* w3       = (const float*)d_in[9];
    const float* gctx     = (const float*)d_in[10];
    const float* gq       = (const float*)d_in[11];
    const float* gff      = (const float*)d_in[12];
    const float* noise    = (const float*)d_in[13];
    const int*   positions= (const int*)d_in[14];
    const float* tau      = (const float*)d_in[15];
    const float* rs       = (const float*)d_in[16];
    const float* gns      = (const float*)d_in[17];

    const int SMEM_SPLIT  = 2 * 3 * TILE_BYTES;   // 110592
    const int SMEM_SINGLE = 2 * 2 * TILE_BYTES;   // 73728
    cudaFuncSetAttribute(fp16_gemm<true>,  cudaFuncAttributeMaxDynamicSharedMemorySize, SMEM_SPLIT);
    cudaFuncSetAttribute(fp16_gemm<false>, cudaFuncAttributeMaxDynamicSharedMemorySize, SMEM_SINGLE);

    #define SYM(v, s) do { void* _p; cudaGetSymbolAddress(&_p, s); v = (decltype(v))_p; } while (0)
    fp16 *wqT,*wkT,*wvT,*wcT,*w13T,*w2T;
    fp16 *nctx_h,*nctx_l,*k1,*vT,*nq_h,*nq_l,*q_h,*q_l,*z1,*attn1,*h1,*p1;
    float *vf,*yf,*ao,*invf;
    SYM(wqT,g_wqT); SYM(wkT,g_wkT); SYM(wvT,g_wvT); SYM(wcT,g_wcT);
    SYM(w13T,g_w13T); SYM(w2T,g_w2T);
    SYM(nctx_h,g_nctx_h); SYM(nctx_l,g_nctx_l);
    SYM(k1,g_k); SYM(vT,g_vT);
    SYM(nq_h,g_nq_h); SYM(nq_l,g_nq_l); SYM(q_h,g_q_h); SYM(q_l,g_q_l);
    SYM(z1,g_z1); SYM(attn1,g_attn1); SYM(h1,g_h1); SYM(p1,g_p1);
    SYM(vf,g_vf); SYM(yf,g_yf); SYM(ao,g_ao);
    SYM(invf,g_invf);
    #undef SYM

    float* out_cb  = (float*)d_out;
    float* out_la  = out_cb  + (size_t)MM * DD;
    float* out_lat = out_la  + (size_t)MM * CC;
    float* out_z   = out_lat + (size_t)MM * CC;

    const float inv_scale = 1.0f / 32.0f;   // 1/sqrt(1024)

    // Launch indices (0-based): ncu -s 5 profiles index 6 -> Wq GEMM.
    init_invf_kernel<<<1, 512>>>(invf);                                        // 0
    rmsnorm_h_kernel<<<CC, 256>>>(codebook, gctx, nctx_h, nctx_l);             // 1
    rmsnorm_h_kernel<<<MM, 256>>>(latents, gq, nq_h, nq_l);                    // 2
    transconv_kernel<<<dim3(DD/32, DD/32), 256>>>(Wq, DD, DD, wqT, 1, 0);      // 3
    transconv_kernel<<<dim3(DD/32, DD/32), 256>>>(Wk, DD, DD, wkT, 1, 0);      // 4
    transconv_kernel<<<dim3(DD/32, DD/32), 256>>>(Wv, DD, DD, wvT, 1, 0);      // 5
    // q = rope(nq @ Wq) -> split fp16, fused                                   // 6 (PROFILED)
    fp16_gemm<true><<<dim3(DD/128, MM/128), 256, SMEM_SPLIT>>>(
        nq_h, nq_l, wqT, nullptr, q_h, q_l, 3, MM, DD, DD, 1.f, nullptr, nullptr, positions, invf);

    transconv_kernel<<<dim3(DD/32, DD/32), 256>>>(Wc, DD, DD, wcT, 1, 0);
    transconv_kernel<<<dim3(HH/32, DD/32), 256>>>(w1, DD, HH, w13T, 2, 0);  // even rows
    transconv_kernel<<<dim3(HH/32, DD/32), 256>>>(w3, DD, HH, w13T, 2, 1);  // odd rows
    transconv_kernel<<<dim3(DD/32, HH/32), 256>>>(w2, HH, DD, w2T, 1, 0);

    // --- context path ---
    // k = rope(nctx @ Wk) -> single fp16, fused
    fp16_gemm<true><<<dim3(DD/128, CC/128), 256, SMEM_SPLIT>>>(
        nctx_h, nctx_l, wkT, nullptr, k1, nullptr, 4, CC, DD, DD, 1.f, nullptr, nullptr, positions, invf);
    fp16_gemm<true><<<dim3(DD/128, CC/128), 256, SMEM_SPLIT>>>(
        nctx_h, nctx_l, wvT, vf, nullptr, nullptr, 0, CC, DD, DD, 1.f, bv, nullptr, nullptr, nullptr);
    transconv_kernel<<<dim3(DD/32, CC/32), 256>>>(vf, CC, DD, vT, 1, 0);

    // log_alpha = q @ k^T / 32
    fp16_gemm<true><<<dim3(CC/128, MM/128), 256, SMEM_SPLIT>>>(
        q_h, q_l, k1, out_la, nullptr, nullptr, 0, MM, CC, DD, inv_scale, nullptr, nullptr, nullptr, nullptr);

    // gumbel + softmax
    gumbel_softmax_kernel<<<MM, 256>>>(out_la, noise, tau, gns, out_lat, out_z, z1);

    // --- attn / FFN chain (single A) ---
    fp16_gemm<false><<<dim3(DD/128, MM/128), 256, SMEM_SINGLE>>>(
        z1, nullptr, vT, nullptr, attn1, nullptr, 1, MM, DD, CC, 1.f, nullptr, nullptr, nullptr, nullptr);
    fp16_gemm<false><<<dim3(DD/128, MM/128), 256, SMEM_SINGLE>>>(
        attn1, nullptr, wcT, yf, nullptr, nullptr, 0, MM, DD, DD, 1.f, nullptr, nullptr, nullptr, nullptr);
    residual_rms_kernel<<<MM, 256>>>(latents, yf, rs, gff, ao, h1);
    fp16_gemm<false><<<dim3(HH2/128, MM/128), 256, SMEM_SINGLE>>>(
        h1, nullptr, w13T, nullptr, p1, nullptr, 2, MM, HH2, DD, 1.f, nullptr, nullptr, nullptr, nullptr);
    fp16_gemm<false><<<dim3(DD/128, MM/128), 256, SMEM_SINGLE>>>(
        p1, nullptr, w2T, out_cb, nullptr, nullptr, 0, MM, DD, HH, 1.f, nullptr, ao, nullptr, nullptr);
}